// round 1
// baseline (speedup 1.0000x reference)
#include <cuda_runtime.h>
#include <cstdint>
#include <cstddef>

#define BB 16
#define NN 1024
#define UU 64
// d_in = 2*U*(K+1) = 384

// ---------------- device scratch (no allocations allowed) ----------------
__device__ float g_adj[(size_t)BB * NN * NN];        // 64 MB
__device__ float g_d0[BB * NN];                      // colsum+1  (for A0 rows)
__device__ float g_d1[BB * NN];                      // rowsum+1  (for A1 rows)
__device__ float g_Y0[(size_t)BB * NN * 128];        // adj  @ [x,h]
__device__ float g_Y1[(size_t)BB * NN * 128];        // adjT @ [x,h]
__device__ float g_Y0p[(size_t)BB * NN * 64];        // adj  @ (r*h)
__device__ float g_Y1p[(size_t)BB * NN * 64];        // adjT @ (r*h)
__device__ float g_u[(size_t)BB * NN * 64];          // update gate
__device__ float g_rh[(size_t)BB * NN * 64];         // r * h
__device__ float g_Wg[128 * 384];                    // effective gate weights
__device__ float g_Wc[64 * 384];                     // effective candidate weights
__device__ float g_bg[128];
__device__ float g_bc[64];

// ---------------- prep: effective weights ----------------
// diffusion stack for K=2 is [x, Ax, Ax]  (reference appends prev twice),
// so per output c: w_x[f] = W[c,3f], w_m[f] = W[c,3f+1] + W[c,3f+2].
// Gate combines gconv(A0,W0) + gconv(A1,W1):
//   k in [0,128)   : X term,  W0[c,3f] + W1[c,3f]
//   k in [128,256) : M0 term, W0[c,3f+1] + W0[c,3f+2]
//   k in [256,384) : M1 term, W1[c,3f+1] + W1[c,3f+2]
__global__ void prep_kernel(const float* __restrict__ W0, const float* __restrict__ b0,
                            const float* __restrict__ W1, const float* __restrict__ b1,
                            const float* __restrict__ Wc0, const float* __restrict__ bc0,
                            const float* __restrict__ Wc1, const float* __restrict__ bc1) {
    int stride = gridDim.x * blockDim.x;
    int t0 = blockIdx.x * blockDim.x + threadIdx.x;
    for (int idx = t0; idx < 128 * 384; idx += stride) {
        int c = idx / 384, k = idx % 384;
        int reg = k >> 7, f = k & 127;
        float w;
        if (reg == 0)      w = W0[c * 384 + 3 * f]     + W1[c * 384 + 3 * f];
        else if (reg == 1) w = W0[c * 384 + 3 * f + 1] + W0[c * 384 + 3 * f + 2];
        else               w = W1[c * 384 + 3 * f + 1] + W1[c * 384 + 3 * f + 2];
        g_Wg[idx] = w;
    }
    for (int idx = t0; idx < 64 * 384; idx += stride) {
        int c = idx / 384, k = idx % 384;
        int reg = k >> 7, f = k & 127;
        float w;
        if (reg == 0)      w = Wc0[c * 384 + 3 * f]     + Wc1[c * 384 + 3 * f];
        else if (reg == 1) w = Wc0[c * 384 + 3 * f + 1] + Wc0[c * 384 + 3 * f + 2];
        else               w = Wc1[c * 384 + 3 * f + 1] + Wc1[c * 384 + 3 * f + 2];
        g_Wc[idx] = w;
    }
    if (t0 < 128) g_bg[t0] = b0[t0] + b1[t0];
    if (t0 < 64)  g_bc[t0] = bc0[t0] + bc1[t0];
}

// ---------------- gumbel softmax + adj + row sums ----------------
// adj[b,i,j] = softmax_0((logits+noise)/TAU) = sigmoid((z0-z1)/TAU), TAU=0.5
// d1[b,i] = rowsum_i(adj) + 1   (deterministic tree: warp shuffle + fixed-order smem sum)
__global__ void gumbel_kernel(const float* __restrict__ logits, const float* __restrict__ unoise) {
    int b = blockIdx.y;
    int i0 = blockIdx.x * 32;
    int t = threadIdx.x;
    int lane = t & 31, w = t >> 5;
    __shared__ float ws[32][8];
    const float2* lg = (const float2*)logits + (size_t)b * NN * NN;
    const float2* un = (const float2*)unoise + (size_t)b * NN * NN;
    float* adj = g_adj + (size_t)b * NN * NN;
    for (int ii = 0; ii < 32; ii++) {
        size_t base = (size_t)(i0 + ii) * NN;
        float rp = 0.f;
#pragma unroll
        for (int q = 0; q < 4; q++) {
            int j = t + q * 256;
            float2 L = lg[base + j];
            float2 Uv = un[base + j];
            float n0 = -logf(1e-10f - logf(Uv.x + 1e-10f));
            float n1 = -logf(1e-10f - logf(Uv.y + 1e-10f));
            float z = (L.x + n0) - (L.y + n1);
            float a = 1.f / (1.f + expf(-2.f * z));
            adj[base + j] = a;
            rp += a;
        }
#pragma unroll
        for (int off = 16; off; off >>= 1) rp += __shfl_down_sync(0xffffffffu, rp, off);
        if (lane == 0) ws[ii][w] = rp;
    }
    __syncthreads();
    if (t < 32) {
        float s = 0.f;
#pragma unroll
        for (int q = 0; q < 8; q++) s += ws[t][q];
        g_d1[b * NN + i0 + t] = s + 1.0f;
    }
}

// ---------------- column sums (deterministic, no atomics) ----------------
// d0[b,j] = colsum_j(adj) + 1
__global__ void colsum_kernel() {
    int b = blockIdx.y;
    int jj = threadIdx.x & 63;
    int j = blockIdx.x * 64 + jj;
    int qt = threadIdx.x >> 6;  // 0..3, each sums 256 rows
    const float* adj = g_adj + (size_t)b * NN * NN;
    float s = 0.f;
    int iend = qt * 256 + 256;
    for (int i = qt * 256; i < iend; i++) s += adj[(size_t)i * NN + j];
    __shared__ float ps[4][64];
    ps[qt][jj] = s;
    __syncthreads();
    if (qt == 0) {
        float tot = ps[0][jj] + ps[1][jj] + ps[2][jj] + ps[3][jj];
        g_d0[b * NN + j] = tot + 1.0f;
    }
}

// ---------------- batched GEMM against adjacency ----------------
// PASS=0: C[b,i,c] (c<128) = sum_k Aeff[i,k] * X[k,c], X=[inputs|hx]  -> g_Y0/g_Y1
// PASS=1: NC=64, X = g_rh                                            -> g_Y0p/g_Y1p
// TRANS: Aeff = adjT. Block tile 128 x NC, thread micro-tile 8 x (NC/16), K-tile 32.
template <bool TRANS, int PASS>
__global__ __launch_bounds__(256) void adj_gemm_kernel(const float* __restrict__ B0,
                                                       const float* __restrict__ B1) {
    constexpr int NC = (PASS == 0) ? 128 : 64;
    constexpr int TN = NC / 16;
    constexpr int MT = 128, KT = 32;
    __shared__ float As[KT][MT + 4];
    __shared__ float Bs[KT][NC];
    int b = blockIdx.y;
    int i0 = blockIdx.x * MT;
    int t = threadIdx.x;
    int ty = t >> 4, tx = t & 15;
    const float* adj = g_adj + (size_t)b * NN * NN;
    float acc[8][TN];
#pragma unroll
    for (int m = 0; m < 8; m++)
#pragma unroll
        for (int n = 0; n < TN; n++) acc[m][n] = 0.f;

    for (int k0 = 0; k0 < NN; k0 += KT) {
        if (!TRANS) {
            // tile adj[i0+ii][k0+kk], ii in 128, kk in 32
#pragma unroll
            for (int p = 0; p < 4; p++) {
                int ii = (t >> 3) + p * 32;
                int kq = (t & 7) << 2;
                float4 v = *(const float4*)(adj + (size_t)(i0 + ii) * NN + (k0 + kq));
                As[kq + 0][ii] = v.x; As[kq + 1][ii] = v.y;
                As[kq + 2][ii] = v.z; As[kq + 3][ii] = v.w;
            }
        } else {
            // Aeff[ii][kk] = adj[k0+kk][i0+ii]: gmem rows kk (32) x 128 floats
#pragma unroll
            for (int p = 0; p < 4; p++) {
                int kk = (t >> 5) + (p << 3);
                int i4 = (t & 31) << 2;
                float4 v = *(const float4*)(adj + (size_t)(k0 + kk) * NN + (i0 + i4));
                As[kk][i4 + 0] = v.x; As[kk][i4 + 1] = v.y;
                As[kk][i4 + 2] = v.z; As[kk][i4 + 3] = v.w;
            }
        }
        if (PASS == 0) {
#pragma unroll
            for (int p = 0; p < 4; p++) {
                int kk = (t >> 5) + (p << 3);
                int c4 = (t & 31) << 2;
                size_t r = (size_t)(b * NN + k0 + kk);
                float4 v = (c4 < 64) ? *(const float4*)(B0 + r * 64 + c4)
                                     : *(const float4*)(B1 + r * 64 + (c4 - 64));
                *(float4*)&Bs[kk][c4] = v;
            }
        } else {
#pragma unroll
            for (int p = 0; p < 2; p++) {
                int kk = (t >> 4) + (p << 4);
                int c4 = (t & 15) << 2;
                size_t r = (size_t)(b * NN + k0 + kk);
                float4 v = *(const float4*)(g_rh + r * 64 + c4);
                *(float4*)&Bs[kk][c4] = v;
            }
        }
        __syncthreads();
#pragma unroll
        for (int kk = 0; kk < KT; kk++) {
            float a[8], bb[TN];
#pragma unroll
            for (int m = 0; m < 8; m++) a[m] = As[kk][ty * 8 + m];
#pragma unroll
            for (int n = 0; n < TN; n++) bb[n] = Bs[kk][tx * TN + n];
#pragma unroll
            for (int m = 0; m < 8; m++)
#pragma unroll
                for (int n = 0; n < TN; n++) acc[m][n] = fmaf(a[m], bb[n], acc[m][n]);
        }
        __syncthreads();
    }
    float* out;
    if (PASS == 0) out = TRANS ? g_Y1 : g_Y0;
    else           out = TRANS ? g_Y1p : g_Y0p;
#pragma unroll
    for (int m = 0; m < 8; m++) {
        size_t r = (size_t)(b * NN + i0 + ty * 8 + m);
#pragma unroll
        for (int n = 0; n < TN; n += 4) {
            float4 v = make_float4(acc[m][n], acc[m][n + 1], acc[m][n + 2], acc[m][n + 3]);
            *(float4*)(out + r * NC + tx * TN + n) = v;
        }
    }
}

// ---------------- gate: value = sigmoid(Xeff @ Wg^T + bg); emit u and r*h ----------------
// Xeff[r,k]: k<128 -> X=[inputs|hx]; 128..255 -> (X+Y0)/d0; 256..383 -> (X+Y1)/d1
__global__ __launch_bounds__(256) void gate_kernel(const float* __restrict__ inputs,
                                                   const float* __restrict__ hx) {
    constexpr int KT = 32;
    __shared__ float Xs[KT][64 + 4];
    __shared__ float Ws[KT][128 + 4];
    int r0 = blockIdx.x * 64;
    int t = threadIdx.x, ty = t >> 4, tx = t & 15;
    float acc[4][8];
#pragma unroll
    for (int m = 0; m < 4; m++)
#pragma unroll
        for (int n = 0; n < 8; n++) acc[m][n] = 0.f;

    for (int k0 = 0; k0 < 384; k0 += KT) {
        int reg = k0 >> 7;
#pragma unroll
        for (int p = 0; p < 2; p++) {
            int ii = (t >> 3) + p * 32;
            int kq = (t & 7) << 2;
            int r = r0 + ii;
            int f = (k0 + kq) & 127;
            float4 xv = (f < 64) ? *(const float4*)(inputs + (size_t)r * 64 + f)
                                 : *(const float4*)(hx + (size_t)r * 64 + (f - 64));
            if (reg == 1) {
                float4 y = *(const float4*)(g_Y0 + (size_t)r * 128 + f);
                float di = 1.f / g_d0[r];
                xv.x = (xv.x + y.x) * di; xv.y = (xv.y + y.y) * di;
                xv.z = (xv.z + y.z) * di; xv.w = (xv.w + y.w) * di;
            } else if (reg == 2) {
                float4 y = *(const float4*)(g_Y1 + (size_t)r * 128 + f);
                float di = 1.f / g_d1[r];
                xv.x = (xv.x + y.x) * di; xv.y = (xv.y + y.y) * di;
                xv.z = (xv.z + y.z) * di; xv.w = (xv.w + y.w) * di;
            }
            Xs[kq + 0][ii] = xv.x; Xs[kq + 1][ii] = xv.y;
            Xs[kq + 2][ii] = xv.z; Xs[kq + 3][ii] = xv.w;
        }
#pragma unroll
        for (int p = 0; p < 4; p++) {
            int c = (t >> 3) + p * 32;
            int kq = (t & 7) << 2;
            float4 wv = *(const float4*)(g_Wg + c * 384 + k0 + kq);
            Ws[kq + 0][c] = wv.x; Ws[kq + 1][c] = wv.y;
            Ws[kq + 2][c] = wv.z; Ws[kq + 3][c] = wv.w;
        }
        __syncthreads();
#pragma unroll
        for (int kk = 0; kk < KT; kk++) {
            float a[4], wv[8];
#pragma unroll
            for (int m = 0; m < 4; m++) a[m] = Xs[kk][ty * 4 + m];
#pragma unroll
            for (int n = 0; n < 8; n++) wv[n] = Ws[kk][tx * 8 + n];
#pragma unroll
            for (int m = 0; m < 4; m++)
#pragma unroll
                for (int n = 0; n < 8; n++) acc[m][n] = fmaf(a[m], wv[n], acc[m][n]);
        }
        __syncthreads();
    }
#pragma unroll
    for (int m = 0; m < 4; m++) {
        size_t r = (size_t)(r0 + ty * 4 + m);
#pragma unroll
        for (int n = 0; n < 8; n++) {
            int c = tx * 8 + n;
            float v = 1.f / (1.f + expf(-(acc[m][n] + g_bg[c])));
            if (c < 64) g_rh[r * 64 + c] = v * hx[r * 64 + c];
            else        g_u[r * 64 + (c - 64)] = v;
        }
    }
}

// ---------------- final: c = tanh(X2eff @ Wc^T + bc); out = u*h + (1-u)*c ----------------
// X2eff[r,k]: k<128 -> [inputs|rh]; 128..255 -> (X2 + [Y0|Y0p])/d0; 256..383 -> (X2 + [Y1|Y1p])/d1
__global__ __launch_bounds__(256) void final_kernel(const float* __restrict__ inputs,
                                                    const float* __restrict__ hx,
                                                    float* __restrict__ out) {
    constexpr int KT = 32;
    __shared__ float Xs[KT][64 + 4];
    __shared__ float Ws[KT][64 + 4];
    int r0 = blockIdx.x * 64;
    int t = threadIdx.x, ty = t >> 4, tx = t & 15;
    float acc[4][4];
#pragma unroll
    for (int m = 0; m < 4; m++)
#pragma unroll
        for (int n = 0; n < 4; n++) acc[m][n] = 0.f;

    for (int k0 = 0; k0 < 384; k0 += KT) {
        int reg = k0 >> 7;
#pragma unroll
        for (int p = 0; p < 2; p++) {
            int ii = (t >> 3) + p * 32;
            int kq = (t & 7) << 2;
            int r = r0 + ii;
            int f = (k0 + kq) & 127;
            float4 xv = (f < 64) ? *(const float4*)(inputs + (size_t)r * 64 + f)
                                 : *(const float4*)(g_rh + (size_t)r * 64 + (f - 64));
            if (reg == 1) {
                float4 y = (f < 64) ? *(const float4*)(g_Y0 + (size_t)r * 128 + f)
                                    : *(const float4*)(g_Y0p + (size_t)r * 64 + (f - 64));
                float di = 1.f / g_d0[r];
                xv.x = (xv.x + y.x) * di; xv.y = (xv.y + y.y) * di;
                xv.z = (xv.z + y.z) * di; xv.w = (xv.w + y.w) * di;
            } else if (reg == 2) {
                float4 y = (f < 64) ? *(const float4*)(g_Y1 + (size_t)r * 128 + f)
                                    : *(const float4*)(g_Y1p + (size_t)r * 64 + (f - 64));
                float di = 1.f / g_d1[r];
                xv.x = (xv.x + y.x) * di; xv.y = (xv.y + y.y) * di;
                xv.z = (xv.z + y.z) * di; xv.w = (xv.w + y.w) * di;
            }
            Xs[kq + 0][ii] = xv.x; Xs[kq + 1][ii] = xv.y;
            Xs[kq + 2][ii] = xv.z; Xs[kq + 3][ii] = xv.w;
        }
#pragma unroll
        for (int p = 0; p < 2; p++) {
            int c = (t >> 3) + p * 32;
            int kq = (t & 7) << 2;
            float4 wv = *(const float4*)(g_Wc + c * 384 + k0 + kq);
            Ws[kq + 0][c] = wv.x; Ws[kq + 1][c] = wv.y;
            Ws[kq + 2][c] = wv.z; Ws[kq + 3][c] = wv.w;
        }
        __syncthreads();
#pragma unroll
        for (int kk = 0; kk < KT; kk++) {
            float a[4], wv[4];
#pragma unroll
            for (int m = 0; m < 4; m++) a[m] = Xs[kk][ty * 4 + m];
#pragma unroll
            for (int n = 0; n < 4; n++) wv[n] = Ws[kk][tx * 4 + n];
#pragma unroll
            for (int m = 0; m < 4; m++)
#pragma unroll
                for (int n = 0; n < 4; n++) acc[m][n] = fmaf(a[m], wv[n], acc[m][n]);
        }
        __syncthreads();
    }
#pragma unroll
    for (int m = 0; m < 4; m++) {
        size_t r = (size_t)(r0 + ty * 4 + m);
#pragma unroll
        for (int n = 0; n < 4; n++) {
            int c = tx * 4 + n;
            float cv = tanhf(acc[m][n] + g_bc[c]);
            float u = g_u[r * 64 + c];
            float h = hx[r * 64 + c];
            out[r * 64 + c] = u * h + (1.f - u) * cv;
        }
    }
}

// ---------------- launch ----------------
extern "C" void kernel_launch(void* const* d_in, const int* in_sizes, int n_in,
                              void* d_out, int out_size) {
    const float* logits = (const float*)d_in[0];
    const float* unoise = (const float*)d_in[1];
    const float* inputs = (const float*)d_in[2];
    const float* hx     = (const float*)d_in[3];
    const float* W0  = (const float*)d_in[4];
    const float* b0  = (const float*)d_in[5];
    const float* W1  = (const float*)d_in[6];
    const float* b1  = (const float*)d_in[7];
    const float* Wc0 = (const float*)d_in[8];
    const float* bc0 = (const float*)d_in[9];
    const float* Wc1 = (const float*)d_in[10];
    const float* bc1 = (const float*)d_in[11];
    float* out = (float*)d_out;

    prep_kernel<<<48, 256>>>(W0, b0, W1, b1, Wc0, bc0, Wc1, bc1);
    gumbel_kernel<<<dim3(32, BB), 256>>>(logits, unoise);
    colsum_kernel<<<dim3(16, BB), 256>>>();
    adj_gemm_kernel<false, 0><<<dim3(8, BB), 256>>>(inputs, hx);
    adj_gemm_kernel<true, 0><<<dim3(8, BB), 256>>>(inputs, hx);
    gate_kernel<<<256, 256>>>(inputs, hx);
    adj_gemm_kernel<false, 1><<<dim3(8, BB), 256>>>(nullptr, nullptr);
    adj_gemm_kernel<true, 1><<<dim3(8, BB), 256>>>(nullptr, nullptr);
    final_kernel<<<256, 256>>>(inputs, hx, out);
}

// round 4
// speedup vs baseline: 1.1565x; 1.1565x over previous
#include <cuda_runtime.h>
#include <cstdint>
#include <cstddef>

#define BB 16
#define NN 1024
#define UU 64
// d_in = 2*U*(K+1) = 384

// ---------------- device scratch (no allocations allowed) ----------------
__device__ float g_adj[(size_t)BB * NN * NN];        // 64 MB (tf32-rounded values)
__device__ float g_d0[BB * NN];                      // colsum+1  (for A0 rows)
__device__ float g_d1[BB * NN];                      // rowsum+1  (for A1 rows)
__device__ float g_Y0[(size_t)BB * NN * 128];        // adj  @ [x,h]
__device__ float g_Y1[(size_t)BB * NN * 128];        // adjT @ [x,h]
__device__ float g_Y0p[(size_t)BB * NN * 64];        // adj  @ (r*h)
__device__ float g_Y1p[(size_t)BB * NN * 64];        // adjT @ (r*h)
__device__ float g_u[(size_t)BB * NN * 64];          // update gate
__device__ float g_rh[(size_t)BB * NN * 64];         // r * h
__device__ float g_Wg[128 * 384];                    // effective gate weights
__device__ float g_Wc[64 * 384];                     // effective candidate weights
__device__ float g_bg[128];
__device__ float g_bc[64];

// cvt.rna.tf32.f32 requires a .b32 destination register: use "=r", then
// reinterpret (tf32 bit pattern is a valid fp32 with low mantissa zeroed).
__device__ __forceinline__ float tf32r(float x) {
    uint32_t r;
    asm("cvt.rna.tf32.f32 %0, %1;" : "=r"(r) : "f"(x));
    return __uint_as_float(r);
}

__device__ __forceinline__ void mma_tf32(float c[4], float a0, float a1, float a2, float a3,
                                         float b0, float b1) {
    asm volatile(
        "mma.sync.aligned.m16n8k8.row.col.f32.tf32.tf32.f32 "
        "{%0,%1,%2,%3},{%4,%5,%6,%7},{%8,%9},{%0,%1,%2,%3};"
        : "+f"(c[0]), "+f"(c[1]), "+f"(c[2]), "+f"(c[3])
        : "r"(__float_as_uint(a0)), "r"(__float_as_uint(a1)),
          "r"(__float_as_uint(a2)), "r"(__float_as_uint(a3)),
          "r"(__float_as_uint(b0)), "r"(__float_as_uint(b1)));
}

// ---------------- prep: effective weights ----------------
// diffusion stack for K=2 is [x, Ax, Ax] (reference appends prev twice),
// so per output c: w_x[f] = W[c,3f], w_m[f] = W[c,3f+1] + W[c,3f+2].
__global__ void prep_kernel(const float* __restrict__ W0, const float* __restrict__ b0,
                            const float* __restrict__ W1, const float* __restrict__ b1,
                            const float* __restrict__ Wc0, const float* __restrict__ bc0,
                            const float* __restrict__ Wc1, const float* __restrict__ bc1) {
    int stride = gridDim.x * blockDim.x;
    int t0 = blockIdx.x * blockDim.x + threadIdx.x;
    for (int idx = t0; idx < 128 * 384; idx += stride) {
        int c = idx / 384, k = idx % 384;
        int reg = k >> 7, f = k & 127;
        float w;
        if (reg == 0)      w = W0[c * 384 + 3 * f]     + W1[c * 384 + 3 * f];
        else if (reg == 1) w = W0[c * 384 + 3 * f + 1] + W0[c * 384 + 3 * f + 2];
        else               w = W1[c * 384 + 3 * f + 1] + W1[c * 384 + 3 * f + 2];
        g_Wg[idx] = w;
    }
    for (int idx = t0; idx < 64 * 384; idx += stride) {
        int c = idx / 384, k = idx % 384;
        int reg = k >> 7, f = k & 127;
        float w;
        if (reg == 0)      w = Wc0[c * 384 + 3 * f]     + Wc1[c * 384 + 3 * f];
        else if (reg == 1) w = Wc0[c * 384 + 3 * f + 1] + Wc0[c * 384 + 3 * f + 2];
        else               w = Wc1[c * 384 + 3 * f + 1] + Wc1[c * 384 + 3 * f + 2];
        g_Wc[idx] = w;
    }
    if (t0 < 128) g_bg[t0] = b0[t0] + b1[t0];
    if (t0 < 64)  g_bc[t0] = bc0[t0] + bc1[t0];
}

// ---------------- gumbel softmax + adj (tf32-rounded) + row sums ----------------
// adj[b,i,j] = sigmoid((z0-z1)*2), z = logit + gumbel noise; TAU=0.5.
// d1[b,i] = rowsum_i(adj) + 1, deterministic fixed-order reduction.
__global__ void gumbel_kernel(const float* __restrict__ logits, const float* __restrict__ unoise) {
    int b = blockIdx.y;
    int i0 = blockIdx.x * 32;
    int t = threadIdx.x;
    int lane = t & 31, w = t >> 5;
    __shared__ float ws[32][8];
    const float2* lg = (const float2*)logits + (size_t)b * NN * NN;
    const float2* un = (const float2*)unoise + (size_t)b * NN * NN;
    float* adj = g_adj + (size_t)b * NN * NN;
    for (int ii = 0; ii < 32; ii++) {
        size_t base = (size_t)(i0 + ii) * NN;
        float rp = 0.f;
#pragma unroll
        for (int q = 0; q < 4; q++) {
            int j = t + q * 256;
            float2 L = lg[base + j];
            float2 Uv = un[base + j];
            float n0 = -__logf(1e-10f - __logf(Uv.x + 1e-10f));
            float n1 = -__logf(1e-10f - __logf(Uv.y + 1e-10f));
            float z = (L.x + n0) - (L.y + n1);
            float a = tf32r(1.f / (1.f + __expf(-2.f * z)));
            adj[base + j] = a;
            rp += a;
        }
#pragma unroll
        for (int off = 16; off; off >>= 1) rp += __shfl_down_sync(0xffffffffu, rp, off);
        if (lane == 0) ws[ii][w] = rp;
    }
    __syncthreads();
    if (t < 32) {
        float s = 0.f;
#pragma unroll
        for (int q = 0; q < 8; q++) s += ws[t][q];
        g_d1[b * NN + i0 + t] = s + 1.0f;
    }
}

// ---------------- column sums (deterministic, no atomics) ----------------
__global__ void colsum_kernel() {
    int b = blockIdx.y;
    int jj = threadIdx.x & 63;
    int j = blockIdx.x * 64 + jj;
    int qt = threadIdx.x >> 6;  // 0..3, each sums 256 rows
    const float* adj = g_adj + (size_t)b * NN * NN;
    float s = 0.f;
    int iend = qt * 256 + 256;
    for (int i = qt * 256; i < iend; i++) s += adj[(size_t)i * NN + j];
    __shared__ float ps[4][64];
    ps[qt][jj] = s;
    __syncthreads();
    if (qt == 0) {
        float tot = ps[0][jj] + ps[1][jj] + ps[2][jj] + ps[3][jj];
        g_d0[b * NN + j] = tot + 1.0f;
    }
}

// ---------------- batched GEMM against adjacency: tensor-core tf32 mma ----------------
// C[b,i,c] = sum_k Aeff[i,k] * X[k,c], Aeff = adj (or adjT when TRANS).
// CTA tile 64 (i) x 64 (c), K-tile 32, 128 threads = 4 warps (2m x 2n, warp 32x32).
// Shared tiles stored K-permuted: c' = (k&3)*8 + (k>>2), row stride 36 floats, so
// a thread's whole K-tile fragment run is 2 contiguous LDS.128 (conflict-free).
// PASS=0: X = [inputs|hx] (source picked by blockIdx.y), out stride 128 -> g_Y0/g_Y1.
// PASS=1: X = g_rh, out stride 64 -> g_Y0p/g_Y1p.
template <bool TRANS, int PASS>
__global__ __launch_bounds__(128) void adj_gemm_mma(const float* __restrict__ Xin,
                                                    const float* __restrict__ Xh) {
    constexpr int STR = 36;
    __shared__ float As2[64 * STR];
    __shared__ float Bs2[64 * STR];
    int b = blockIdx.z;
    int i0 = blockIdx.x * 64;
    int c0 = blockIdx.y * 64;
    const float* adj = g_adj + (size_t)b * NN * NN;
    const float* Bsrc;
    if (PASS == 0) Bsrc = (blockIdx.y == 0 ? Xin : Xh) + (size_t)b * NN * 64;
    else           Bsrc = g_rh + (size_t)b * NN * 64;

    int t = threadIdx.x;
    int wid = t >> 5, lane = t & 31;
    int wm = wid >> 1, wn = wid & 1;
    int lg = lane >> 2, l4 = lane & 3;

    float acc[2][4][4];
#pragma unroll
    for (int mt = 0; mt < 2; mt++)
#pragma unroll
        for (int nt = 0; nt < 4; nt++)
#pragma unroll
            for (int q = 0; q < 4; q++) acc[mt][nt][q] = 0.f;

    for (int k0 = 0; k0 < NN; k0 += 32) {
        // --- fill As2: A[m][k] -> As2[m*STR + (k&3)*8 + (k>>2)] ---
        if (!TRANS) {
#pragma unroll
            for (int it = 0; it < 4; it++) {
                int idx = t + it * 128;
                int m = idx >> 3, q = idx & 7;
                float4 v = *(const float4*)(adj + (size_t)(i0 + m) * NN + k0 + q * 4);
                As2[m * STR + q]      = v.x;
                As2[m * STR + 8 + q]  = v.y;
                As2[m * STR + 16 + q] = v.z;
                As2[m * STR + 24 + q] = v.w;
            }
        } else {
#pragma unroll
            for (int it = 0; it < 4; it++) {
                int idx = t + it * 128;
                int k = idx >> 4, mq = (idx & 15) * 4;
                float4 v = *(const float4*)(adj + (size_t)(k0 + k) * NN + i0 + mq);
                int cp = (k & 3) * 8 + (k >> 2);
                As2[(mq + 0) * STR + cp] = v.x;
                As2[(mq + 1) * STR + cp] = v.y;
                As2[(mq + 2) * STR + cp] = v.z;
                As2[(mq + 3) * STR + cp] = v.w;
            }
        }
        // --- fill Bs2: B[k][c] -> Bs2[c*STR + perm(k)], tf32-rounded ---
#pragma unroll
        for (int it = 0; it < 4; it++) {
            int idx = t + it * 128;
            int k = idx >> 4, cq = (idx & 15) * 4;
            float4 v = *(const float4*)(Bsrc + (size_t)(k0 + k) * 64 + cq);
            int cp = (k & 3) * 8 + (k >> 2);
            Bs2[(cq + 0) * STR + cp] = tf32r(v.x);
            Bs2[(cq + 1) * STR + cp] = tf32r(v.y);
            Bs2[(cq + 2) * STR + cp] = tf32r(v.z);
            Bs2[(cq + 3) * STR + cp] = tf32r(v.w);
        }
        __syncthreads();

        // --- load fragments for the whole K-tile ---
        float a[2][2][8];  // [m16 tile][row group lo/hi][k-run]
#pragma unroll
        for (int mt = 0; mt < 2; mt++) {
            int rb = wm * 32 + mt * 16;
            *(float4*)&a[mt][0][0] = *(const float4*)&As2[(rb + lg) * STR + l4 * 8];
            *(float4*)&a[mt][0][4] = *(const float4*)&As2[(rb + lg) * STR + l4 * 8 + 4];
            *(float4*)&a[mt][1][0] = *(const float4*)&As2[(rb + 8 + lg) * STR + l4 * 8];
            *(float4*)&a[mt][1][4] = *(const float4*)&As2[(rb + 8 + lg) * STR + l4 * 8 + 4];
        }
        float brg[4][8];
#pragma unroll
        for (int nt = 0; nt < 4; nt++) {
            int rb = wn * 32 + nt * 8 + lg;
            *(float4*)&brg[nt][0] = *(const float4*)&Bs2[rb * STR + l4 * 8];
            *(float4*)&brg[nt][4] = *(const float4*)&Bs2[rb * STR + l4 * 8 + 4];
        }
        // --- mma: 4 k8 steps x 2 m-tiles x 4 n-tiles ---
#pragma unroll
        for (int s = 0; s < 4; s++)
#pragma unroll
            for (int mt = 0; mt < 2; mt++)
#pragma unroll
                for (int nt = 0; nt < 4; nt++)
                    mma_tf32(acc[mt][nt],
                             a[mt][0][2 * s], a[mt][1][2 * s],
                             a[mt][0][2 * s + 1], a[mt][1][2 * s + 1],
                             brg[nt][2 * s], brg[nt][2 * s + 1]);
        __syncthreads();
    }

    // --- epilogue ---
    constexpr int OSTR = (PASS == 0) ? 128 : 64;
    float* out;
    if (PASS == 0) out = TRANS ? g_Y1 : g_Y0;
    else           out = TRANS ? g_Y1p : g_Y0p;
#pragma unroll
    for (int mt = 0; mt < 2; mt++) {
#pragma unroll
        for (int nt = 0; nt < 4; nt++) {
            int row = i0 + wm * 32 + mt * 16 + lg;
            int col = c0 + wn * 32 + nt * 8 + 2 * l4;
            float2 v01 = make_float2(acc[mt][nt][0], acc[mt][nt][1]);
            float2 v23 = make_float2(acc[mt][nt][2], acc[mt][nt][3]);
            *(float2*)(out + (size_t)(b * NN + row) * OSTR + col) = v01;
            *(float2*)(out + (size_t)(b * NN + row + 8) * OSTR + col) = v23;
        }
    }
}

// ---------------- gate: value = sigmoid(Xeff @ Wg^T + bg); emit u and r*h ----------------
// Xeff[r,k]: k<128 -> X=[inputs|hx]; 128..255 -> (X+Y0)/d0; 256..383 -> (X+Y1)/d1
__global__ __launch_bounds__(256) void gate_kernel(const float* __restrict__ inputs,
                                                   const float* __restrict__ hx) {
    constexpr int KT = 32;
    __shared__ float Xs[KT][64 + 4];
    __shared__ float Ws[KT][128 + 4];
    int r0 = blockIdx.x * 64;
    int t = threadIdx.x, ty = t >> 4, tx = t & 15;
    float acc[4][8];
#pragma unroll
    for (int m = 0; m < 4; m++)
#pragma unroll
        for (int n = 0; n < 8; n++) acc[m][n] = 0.f;

    for (int k0 = 0; k0 < 384; k0 += KT) {
        int reg = k0 >> 7;
#pragma unroll
        for (int p = 0; p < 2; p++) {
            int ii = (t >> 3) + p * 32;
            int kq = (t & 7) << 2;
            int r = r0 + ii;
            int f = (k0 + kq) & 127;
            float4 xv = (f < 64) ? *(const float4*)(inputs + (size_t)r * 64 + f)
                                 : *(const float4*)(hx + (size_t)r * 64 + (f - 64));
            if (reg == 1) {
                float4 y = *(const float4*)(g_Y0 + (size_t)r * 128 + f);
                float di = 1.f / g_d0[r];
                xv.x = (xv.x + y.x) * di; xv.y = (xv.y + y.y) * di;
                xv.z = (xv.z + y.z) * di; xv.w = (xv.w + y.w) * di;
            } else if (reg == 2) {
                float4 y = *(const float4*)(g_Y1 + (size_t)r * 128 + f);
                float di = 1.f / g_d1[r];
                xv.x = (xv.x + y.x) * di; xv.y = (xv.y + y.y) * di;
                xv.z = (xv.z + y.z) * di; xv.w = (xv.w + y.w) * di;
            }
            Xs[kq + 0][ii] = xv.x; Xs[kq + 1][ii] = xv.y;
            Xs[kq + 2][ii] = xv.z; Xs[kq + 3][ii] = xv.w;
        }
#pragma unroll
        for (int p = 0; p < 4; p++) {
            int c = (t >> 3) + p * 32;
            int kq = (t & 7) << 2;
            float4 wv = *(const float4*)(g_Wg + c * 384 + k0 + kq);
            Ws[kq + 0][c] = wv.x; Ws[kq + 1][c] = wv.y;
            Ws[kq + 2][c] = wv.z; Ws[kq + 3][c] = wv.w;
        }
        __syncthreads();
#pragma unroll
        for (int kk = 0; kk < KT; kk++) {
            float a[4], wv[8];
#pragma unroll
            for (int m = 0; m < 4; m++) a[m] = Xs[kk][ty * 4 + m];
#pragma unroll
            for (int n = 0; n < 8; n++) wv[n] = Ws[kk][tx * 8 + n];
#pragma unroll
            for (int m = 0; m < 4; m++)
#pragma unroll
                for (int n = 0; n < 8; n++) acc[m][n] = fmaf(a[m], wv[n], acc[m][n]);
        }
        __syncthreads();
    }
#pragma unroll
    for (int m = 0; m < 4; m++) {
        size_t r = (size_t)(r0 + ty * 4 + m);
#pragma unroll
        for (int n = 0; n < 8; n++) {
            int c = tx * 8 + n;
            float v = 1.f / (1.f + expf(-(acc[m][n] + g_bg[c])));
            if (c < 64) g_rh[r * 64 + c] = v * hx[r * 64 + c];
            else        g_u[r * 64 + (c - 64)] = v;
        }
    }
}

// ---------------- final: c = tanh(X2eff @ Wc^T + bc); out = u*h + (1-u)*c ----------------
__global__ __launch_bounds__(256) void final_kernel(const float* __restrict__ inputs,
                                                    const float* __restrict__ hx,
                                                    float* __restrict__ out) {
    constexpr int KT = 32;
    __shared__ float Xs[KT][64 + 4];
    __shared__ float Ws[KT][64 + 4];
    int r0 = blockIdx.x * 64;
    int t = threadIdx.x, ty = t >> 4, tx = t & 15;
    float acc[4][4];
#pragma unroll
    for (int m = 0; m < 4; m++)
#pragma unroll
        for (int n = 0; n < 4; n++) acc[m][n] = 0.f;

    for (int k0 = 0; k0 < 384; k0 += KT) {
        int reg = k0 >> 7;
#pragma unroll
        for (int p = 0; p < 2; p++) {
            int ii = (t >> 3) + p * 32;
            int kq = (t & 7) << 2;
            int r = r0 + ii;
            int f = (k0 + kq) & 127;
            float4 xv = (f < 64) ? *(const float4*)(inputs + (size_t)r * 64 + f)
                                 : *(const float4*)(g_rh + (size_t)r * 64 + (f - 64));
            if (reg == 1) {
                float4 y = (f < 64) ? *(const float4*)(g_Y0 + (size_t)r * 128 + f)
                                    : *(const float4*)(g_Y0p + (size_t)r * 64 + (f - 64));
                float di = 1.f / g_d0[r];
                xv.x = (xv.x + y.x) * di; xv.y = (xv.y + y.y) * di;
                xv.z = (xv.z + y.z) * di; xv.w = (xv.w + y.w) * di;
            } else if (reg == 2) {
                float4 y = (f < 64) ? *(const float4*)(g_Y1 + (size_t)r * 128 + f)
                                    : *(const float4*)(g_Y1p + (size_t)r * 64 + (f - 64));
                float di = 1.f / g_d1[r];
                xv.x = (xv.x + y.x) * di; xv.y = (xv.y + y.y) * di;
                xv.z = (xv.z + y.z) * di; xv.w = (xv.w + y.w) * di;
            }
            Xs[kq + 0][ii] = xv.x; Xs[kq + 1][ii] = xv.y;
            Xs[kq + 2][ii] = xv.z; Xs[kq + 3][ii] = xv.w;
        }
#pragma unroll
        for (int p = 0; p < 2; p++) {
            int c = (t >> 3) + p * 32;
            int kq = (t & 7) << 2;
            float4 wv = *(const float4*)(g_Wc + c * 384 + k0 + kq);
            Ws[kq + 0][c] = wv.x; Ws[kq + 1][c] = wv.y;
            Ws[kq + 2][c] = wv.z; Ws[kq + 3][c] = wv.w;
        }
        __syncthreads();
#pragma unroll
        for (int kk = 0; kk < KT; kk++) {
            float a[4], wv[4];
#pragma unroll
            for (int m = 0; m < 4; m++) a[m] = Xs[kk][ty * 4 + m];
#pragma unroll
            for (int n = 0; n < 4; n++) wv[n] = Ws[kk][tx * 4 + n];
#pragma unroll
            for (int m = 0; m < 4; m++)
#pragma unroll
                for (int n = 0; n < 4; n++) acc[m][n] = fmaf(a[m], wv[n], acc[m][n]);
        }
        __syncthreads();
    }
#pragma unroll
    for (int m = 0; m < 4; m++) {
        size_t r = (size_t)(r0 + ty * 4 + m);
#pragma unroll
        for (int n = 0; n < 4; n++) {
            int c = tx * 4 + n;
            float cv = tanhf(acc[m][n] + g_bc[c]);
            float u = g_u[r * 64 + c];
            float h = hx[r * 64 + c];
            out[r * 64 + c] = u * h + (1.f - u) * cv;
        }
    }
}

// ---------------- launch ----------------
extern "C" void kernel_launch(void* const* d_in, const int* in_sizes, int n_in,
                              void* d_out, int out_size) {
    const float* logits = (const float*)d_in[0];
    const float* unoise = (const float*)d_in[1];
    const float* inputs = (const float*)d_in[2];
    const float* hx     = (const float*)d_in[3];
    const float* W0  = (const float*)d_in[4];
    const float* b0  = (const float*)d_in[5];
    const float* W1  = (const float*)d_in[6];
    const float* b1  = (const float*)d_in[7];
    const float* Wc0 = (const float*)d_in[8];
    const float* bc0 = (const float*)d_in[9];
    const float* Wc1 = (const float*)d_in[10];
    const float* bc1 = (const float*)d_in[11];
    float* out = (float*)d_out;

    prep_kernel<<<48, 256>>>(W0, b0, W1, b1, Wc0, bc0, Wc1, bc1);
    gumbel_kernel<<<dim3(32, BB), 256>>>(logits, unoise);
    colsum_kernel<<<dim3(16, BB), 256>>>();
    adj_gemm_mma<false, 0><<<dim3(16, 2, BB), 128>>>(inputs, hx);
    adj_gemm_mma<true, 0><<<dim3(16, 2, BB), 128>>>(inputs, hx);
    gate_kernel<<<256, 256>>>(inputs, hx);
    adj_gemm_mma<false, 1><<<dim3(16, 1, BB), 128>>>(inputs, hx);
    adj_gemm_mma<true, 1><<<dim3(16, 1, BB), 128>>>(inputs, hx);
    final_kernel<<<256, 256>>>(inputs, hx, out);
}

// round 5
// speedup vs baseline: 2.3381x; 2.0217x over previous
#include <cuda_runtime.h>
#include <cuda_bf16.h>
#include <cstdint>
#include <cstddef>

#define BB 16
#define NN 1024

// ---------------- device scratch ----------------
__device__ __nv_bfloat16 g_adjh[(size_t)BB * NN * NN];   // 32 MB adjacency (bf16)
__device__ float g_d0[BB * NN];                          // colsum+1
__device__ float g_d1[BB * NN];                          // rowsum+1
__device__ float g_Y0[(size_t)BB * NN * 128];
__device__ float g_Y1[(size_t)BB * NN * 128];
__device__ float g_Y0p[(size_t)BB * NN * 64];
__device__ float g_Y1p[(size_t)BB * NN * 64];
__device__ float g_u[(size_t)BB * NN * 64];
__device__ float g_rh[(size_t)BB * NN * 64];             // fp32 r*h (for final region0)
__device__ __nv_bfloat16 g_xh[(size_t)BB * NN * 128];    // bf16 [inputs|hx]
__device__ __nv_bfloat16 g_rhh[(size_t)BB * NN * 64];    // bf16 r*h (GEMM operand)
__device__ float g_Wg[128 * 384];
__device__ float g_Wc[64 * 384];
__device__ float g_bg[128];
__device__ float g_bc[64];

// ---------------- PTX helpers ----------------
__device__ __forceinline__ void mma_bf16(float* c, uint32_t a0, uint32_t a1, uint32_t a2,
                                         uint32_t a3, uint32_t b0, uint32_t b1) {
    asm volatile(
        "mma.sync.aligned.m16n8k16.row.col.f32.bf16.bf16.f32 "
        "{%0,%1,%2,%3},{%4,%5,%6,%7},{%8,%9},{%0,%1,%2,%3};"
        : "+f"(c[0]), "+f"(c[1]), "+f"(c[2]), "+f"(c[3])
        : "r"(a0), "r"(a1), "r"(a2), "r"(a3), "r"(b0), "r"(b1));
}
__device__ __forceinline__ void ldsm4(uint32_t& r0, uint32_t& r1, uint32_t& r2, uint32_t& r3,
                                      uint32_t a) {
    asm volatile("ldmatrix.sync.aligned.m8n8.x4.shared.b16 {%0,%1,%2,%3},[%4];"
                 : "=r"(r0), "=r"(r1), "=r"(r2), "=r"(r3) : "r"(a));
}
__device__ __forceinline__ void ldsm4t(uint32_t& r0, uint32_t& r1, uint32_t& r2, uint32_t& r3,
                                       uint32_t a) {
    asm volatile("ldmatrix.sync.aligned.m8n8.x4.trans.shared.b16 {%0,%1,%2,%3},[%4];"
                 : "=r"(r0), "=r"(r1), "=r"(r2), "=r"(r3) : "r"(a));
}
__device__ __forceinline__ void cpasync16(uint32_t s, const void* g) {
    asm volatile("cp.async.cg.shared.global [%0],[%1],16;" :: "r"(s), "l"(g));
}
#define CP_COMMIT() asm volatile("cp.async.commit_group;")
#define CP_WAIT(n) asm volatile("cp.async.wait_group %0;" :: "n"(n))

// ---------------- prep: effective weights ----------------
// diffusion stack for K=2 is [x, Ax, Ax]: w_x[f] = W[c,3f], w_m[f] = W[c,3f+1]+W[c,3f+2]
__global__ void prep_kernel(const float* __restrict__ W0, const float* __restrict__ b0,
                            const float* __restrict__ W1, const float* __restrict__ b1,
                            const float* __restrict__ Wc0, const float* __restrict__ bc0,
                            const float* __restrict__ Wc1, const float* __restrict__ bc1) {
    int stride = gridDim.x * blockDim.x;
    int t0 = blockIdx.x * blockDim.x + threadIdx.x;
    for (int idx = t0; idx < 128 * 384; idx += stride) {
        int c = idx / 384, k = idx % 384;
        int reg = k >> 7, f = k & 127;
        float w;
        if (reg == 0)      w = W0[c * 384 + 3 * f]     + W1[c * 384 + 3 * f];
        else if (reg == 1) w = W0[c * 384 + 3 * f + 1] + W0[c * 384 + 3 * f + 2];
        else               w = W1[c * 384 + 3 * f + 1] + W1[c * 384 + 3 * f + 2];
        g_Wg[idx] = w;
    }
    for (int idx = t0; idx < 64 * 384; idx += stride) {
        int c = idx / 384, k = idx % 384;
        int reg = k >> 7, f = k & 127;
        float w;
        if (reg == 0)      w = Wc0[c * 384 + 3 * f]     + Wc1[c * 384 + 3 * f];
        else if (reg == 1) w = Wc0[c * 384 + 3 * f + 1] + Wc0[c * 384 + 3 * f + 2];
        else               w = Wc1[c * 384 + 3 * f + 1] + Wc1[c * 384 + 3 * f + 2];
        g_Wc[idx] = w;
    }
    if (t0 < 128) g_bg[t0] = b0[t0] + b1[t0];
    if (t0 < 64)  g_bc[t0] = bc0[t0] + bc1[t0];
}

// ---------------- convert [inputs|hx] -> bf16 g_xh ----------------
__global__ void convert_x_kernel(const float* __restrict__ inputs, const float* __restrict__ hx) {
    size_t idx = (size_t)blockIdx.x * blockDim.x + threadIdx.x;   // one float4 group
    if (idx >= (size_t)BB * NN * 32) return;
    size_t r = idx >> 5;
    int g = (int)(idx & 31);
    float4 v = (g < 16) ? *(const float4*)(inputs + r * 64 + g * 4)
                        : *(const float4*)(hx + r * 64 + (g - 16) * 4);
    __nv_bfloat162* dst = (__nv_bfloat162*)(g_xh + r * 128 + g * 4);
    dst[0] = __floats2bfloat162_rn(v.x, v.y);
    dst[1] = __floats2bfloat162_rn(v.z, v.w);
}

// ---------------- gumbel softmax -> bf16 adj + row sums ----------------
__global__ void gumbel_kernel(const float* __restrict__ logits, const float* __restrict__ unoise) {
    int b = blockIdx.y;
    int i0 = blockIdx.x * 32;
    int t = threadIdx.x;
    int lane = t & 31, w = t >> 5;
    __shared__ float ws[32][8];
    const float4* lg = (const float4*)(logits + (size_t)b * NN * NN * 2);
    const float4* un = (const float4*)(unoise + (size_t)b * NN * NN * 2);
    __nv_bfloat162* adj2 = (__nv_bfloat162*)g_adjh + (size_t)b * NN * 512;
    for (int ii = 0; ii < 32; ii++) {
        size_t base4 = (size_t)(i0 + ii) * 512;   // 512 float4 (=2048 floats) per row
        float rp = 0.f;
#pragma unroll
        for (int q = 0; q < 2; q++) {
            int jp = t + q * 256;
            float4 L = lg[base4 + jp];
            float4 Uv = un[base4 + jp];
            float n0 = -__logf(1e-10f - __logf(Uv.x + 1e-10f));
            float n1 = -__logf(1e-10f - __logf(Uv.y + 1e-10f));
            float n2 = -__logf(1e-10f - __logf(Uv.z + 1e-10f));
            float n3 = -__logf(1e-10f - __logf(Uv.w + 1e-10f));
            float z0 = (L.x + n0) - (L.y + n1);
            float z1 = (L.z + n2) - (L.w + n3);
            float a0 = 1.f / (1.f + __expf(-2.f * z0));
            float a1 = 1.f / (1.f + __expf(-2.f * z1));
            adj2[base4 + jp] = __floats2bfloat162_rn(a0, a1);
            rp += a0 + a1;
        }
#pragma unroll
        for (int off = 16; off; off >>= 1) rp += __shfl_down_sync(0xffffffffu, rp, off);
        if (lane == 0) ws[ii][w] = rp;
    }
    __syncthreads();
    if (t < 32) {
        float s = 0.f;
#pragma unroll
        for (int q = 0; q < 8; q++) s += ws[t][q];
        g_d1[b * NN + i0 + t] = s + 1.0f;
    }
}

// ---------------- column sums over bf16 adj ----------------
__global__ void colsum_kernel() {
    int b = blockIdx.y;
    int j2 = blockIdx.x * 64 + (threadIdx.x & 63);   // bf162 column, 512 total -> grid.x = 8
    int qt = threadIdx.x >> 6;                       // 0..3, each sums 256 rows
    const __nv_bfloat162* adj2 = (const __nv_bfloat162*)g_adjh + (size_t)b * NN * 512;
    float sx = 0.f, sy = 0.f;
    int iend = qt * 256 + 256;
    for (int i = qt * 256; i < iend; i++) {
        float2 f = __bfloat1622float2(adj2[(size_t)i * 512 + j2]);
        sx += f.x; sy += f.y;
    }
    __shared__ float psx[4][64], psy[4][64];
    psx[qt][threadIdx.x & 63] = sx;
    psy[qt][threadIdx.x & 63] = sy;
    __syncthreads();
    if (qt == 0) {
        int jj = threadIdx.x & 63;
        float tx = psx[0][jj] + psx[1][jj] + psx[2][jj] + psx[3][jj];
        float ty = psy[0][jj] + psy[1][jj] + psy[2][jj] + psy[3][jj];
        g_d0[b * NN + 2 * j2]     = tx + 1.0f;
        g_d0[b * NN + 2 * j2 + 1] = ty + 1.0f;
    }
}

// ---------------- adjacency GEMM: bf16 mma + ldmatrix + cp.async double-buffer ----------
// C[b,i,c] = sum_k Aeff[i,k] * X[k,c];  Aeff = adj (TRANS: adjT).
// CTA 128m x NC, 256 threads = 8 warps (4m x 2n), warp tile 32 x NC/2, K-tile 64.
// Tiles stored gmem-natural, XOR-swizzled (16B chunk c ^= row&7); A frags via ldmatrix
// (TRANS: ldmatrix.trans with a1/a2 reorder), B frags via ldmatrix.trans.
// PASS=0: NC=128, X = g_xh, out g_Y0/g_Y1. PASS=1: NC=64, X = g_rhh, out g_Y0p/g_Y1p.
template <bool TRANS, int PASS>
__global__ __launch_bounds__(256) void adj_gemm_bf16() {
    constexpr int NC = (PASS == 0) ? 128 : 64;
    constexpr int NT = NC / 16;                 // n8 tiles per warp
    constexpr int BS_STAGE = 64 * NC * 2;       // bytes per Bs stage
    extern __shared__ __nv_bfloat16 smem[];
    __nv_bfloat16* As = smem;                   // 2 stages x 16 KB
    __nv_bfloat16* Bsh = smem + 2 * 128 * 64;
    int b = blockIdx.y;
    int i0 = blockIdx.x * 128;
    const __nv_bfloat16* adj = g_adjh + (size_t)b * NN * NN;
    const __nv_bfloat16* Bsrc = ((PASS == 0) ? g_xh : g_rhh) + (size_t)b * NN * NC;
    int t = threadIdx.x, lane = t & 31, wid = t >> 5;
    int wm = wid >> 1, wn = wid & 1;
    uint32_t as_base = (uint32_t)__cvta_generic_to_shared(As);
    uint32_t bs_base = (uint32_t)__cvta_generic_to_shared(Bsh);

    float acc[2][NT][4];
#pragma unroll
    for (int mt = 0; mt < 2; mt++)
#pragma unroll
        for (int nt = 0; nt < NT; nt++)
#pragma unroll
            for (int q = 0; q < 4; q++) acc[mt][nt][q] = 0.f;

    auto fill = [&](int st, int k0) {
        // A: 1024 16B chunks
#pragma unroll
        for (int it = 0; it < 4; it++) {
            int q = t + it * 256;
            if (!TRANS) {
                int m = q >> 3, cc = q & 7;
                uint32_t dst = as_base + st * 16384 + (((m << 3) + (cc ^ (m & 7))) << 4);
                cpasync16(dst, adj + (size_t)(i0 + m) * NN + k0 + cc * 8);
            } else {
                int k = q >> 4, cc = q & 15;
                uint32_t dst = as_base + st * 16384 + (((k << 4) + (cc ^ (k & 7))) << 4);
                cpasync16(dst, adj + (size_t)(k0 + k) * NN + i0 + cc * 8);
            }
        }
        // B
        if (PASS == 0) {
#pragma unroll
            for (int it = 0; it < 4; it++) {
                int q = t + it * 256;
                int k = q >> 4, cc = q & 15;
                uint32_t dst = bs_base + st * BS_STAGE + (((k << 4) + (cc ^ (k & 7))) << 4);
                cpasync16(dst, Bsrc + (size_t)(k0 + k) * 128 + cc * 8);
            }
        } else {
#pragma unroll
            for (int it = 0; it < 2; it++) {
                int q = t + it * 256;
                int k = q >> 3, cc = q & 7;
                uint32_t dst = bs_base + st * BS_STAGE + (((k << 3) + (cc ^ (k & 7))) << 4);
                cpasync16(dst, Bsrc + (size_t)(k0 + k) * 64 + cc * 8);
            }
        }
    };

    fill(0, 0);
    CP_COMMIT();
    for (int kt = 0; kt < 16; kt++) {
        int st = kt & 1;
        if (kt + 1 < 16) {
            fill(st ^ 1, (kt + 1) * 64);
            CP_COMMIT();
            CP_WAIT(1);
        } else {
            CP_WAIT(0);
        }
        __syncthreads();
#pragma unroll
        for (int kk = 0; kk < 4; kk++) {
            uint32_t Af[2][4];
#pragma unroll
            for (int mt = 0; mt < 2; mt++) {
                if (!TRANS) {
                    int r = wm * 32 + mt * 16 + (lane & 15);
                    int cc = (kk << 1) + (lane >> 4);
                    uint32_t a = as_base + st * 16384 + (((r << 3) + (cc ^ (r & 7))) << 4);
                    ldsm4(Af[mt][0], Af[mt][1], Af[mt][2], Af[mt][3], a);
                } else {
                    int r = (kk << 4) + (lane & 15);
                    int cc = ((wm * 32 + mt * 16) >> 3) + (lane >> 4);
                    uint32_t a = as_base + st * 16384 + (((r << 4) + (cc ^ (r & 7))) << 4);
                    uint32_t p0, p1, p2, p3;
                    ldsm4t(p0, p1, p2, p3, a);
                    Af[mt][0] = p0; Af[mt][1] = p2; Af[mt][2] = p1; Af[mt][3] = p3;
                }
            }
            uint32_t Bf[NT][2];
#pragma unroll
            for (int np = 0; np < NT / 2; np++) {
                int r = (kk << 4) + (lane & 15);
                int cc = ((wn * (NC / 2) + np * 16) >> 3) + (lane >> 4);
                uint32_t a = bs_base + st * BS_STAGE + ((r * (NC / 8) + (cc ^ (r & 7))) << 4);
                uint32_t q0, q1, q2, q3;
                ldsm4t(q0, q1, q2, q3, a);
                Bf[2 * np][0] = q0; Bf[2 * np][1] = q1;
                Bf[2 * np + 1][0] = q2; Bf[2 * np + 1][1] = q3;
            }
#pragma unroll
            for (int mt = 0; mt < 2; mt++)
#pragma unroll
                for (int nt = 0; nt < NT; nt++)
                    mma_bf16(acc[mt][nt], Af[mt][0], Af[mt][1], Af[mt][2], Af[mt][3],
                             Bf[nt][0], Bf[nt][1]);
        }
        __syncthreads();
    }

    float* out = (PASS == 0) ? (TRANS ? g_Y1 : g_Y0) : (TRANS ? g_Y1p : g_Y0p);
    int g = lane >> 2, tt = lane & 3;
#pragma unroll
    for (int mt = 0; mt < 2; mt++) {
#pragma unroll
        for (int nt = 0; nt < NT; nt++) {
            int row = i0 + wm * 32 + mt * 16 + g;
            int col = wn * (NC / 2) + nt * 8 + 2 * tt;
            *(float2*)(out + ((size_t)b * NN + row) * NC + col) =
                make_float2(acc[mt][nt][0], acc[mt][nt][1]);
            *(float2*)(out + ((size_t)b * NN + row + 8) * NC + col) =
                make_float2(acc[mt][nt][2], acc[mt][nt][3]);
        }
    }
}

// ---------------- gate: value = sigmoid(Xeff @ Wg^T + bg); emit u, r*h (fp32+bf16) ------
__global__ __launch_bounds__(256) void gate_kernel(const float* __restrict__ inputs,
                                                   const float* __restrict__ hx) {
    constexpr int KT = 32;
    __shared__ float Xs[KT][64 + 4];
    __shared__ float Ws[KT][128 + 4];
    int r0 = blockIdx.x * 64;
    int t = threadIdx.x, ty = t >> 4, tx = t & 15;
    float acc[4][8];
#pragma unroll
    for (int m = 0; m < 4; m++)
#pragma unroll
        for (int n = 0; n < 8; n++) acc[m][n] = 0.f;

    for (int k0 = 0; k0 < 384; k0 += KT) {
        int reg = k0 >> 7;
#pragma unroll
        for (int p = 0; p < 2; p++) {
            int ii = (t >> 3) + p * 32;
            int kq = (t & 7) << 2;
            int r = r0 + ii;
            int f = (k0 + kq) & 127;
            float4 xv = (f < 64) ? *(const float4*)(inputs + (size_t)r * 64 + f)
                                 : *(const float4*)(hx + (size_t)r * 64 + (f - 64));
            if (reg == 1) {
                float4 y = *(const float4*)(g_Y0 + (size_t)r * 128 + f);
                float di = 1.f / g_d0[r];
                xv.x = (xv.x + y.x) * di; xv.y = (xv.y + y.y) * di;
                xv.z = (xv.z + y.z) * di; xv.w = (xv.w + y.w) * di;
            } else if (reg == 2) {
                float4 y = *(const float4*)(g_Y1 + (size_t)r * 128 + f);
                float di = 1.f / g_d1[r];
                xv.x = (xv.x + y.x) * di; xv.y = (xv.y + y.y) * di;
                xv.z = (xv.z + y.z) * di; xv.w = (xv.w + y.w) * di;
            }
            Xs[kq + 0][ii] = xv.x; Xs[kq + 1][ii] = xv.y;
            Xs[kq + 2][ii] = xv.z; Xs[kq + 3][ii] = xv.w;
        }
#pragma unroll
        for (int p = 0; p < 4; p++) {
            int c = (t >> 3) + p * 32;
            int kq = (t & 7) << 2;
            float4 wv = *(const float4*)(g_Wg + c * 384 + k0 + kq);
            Ws[kq + 0][c] = wv.x; Ws[kq + 1][c] = wv.y;
            Ws[kq + 2][c] = wv.z; Ws[kq + 3][c] = wv.w;
        }
        __syncthreads();
#pragma unroll
        for (int kk = 0; kk < KT; kk++) {
            float a[4], wv[8];
#pragma unroll
            for (int m = 0; m < 4; m++) a[m] = Xs[kk][ty * 4 + m];
#pragma unroll
            for (int n = 0; n < 8; n++) wv[n] = Ws[kk][tx * 8 + n];
#pragma unroll
            for (int m = 0; m < 4; m++)
#pragma unroll
                for (int n = 0; n < 8; n++) acc[m][n] = fmaf(a[m], wv[n], acc[m][n]);
        }
        __syncthreads();
    }
#pragma unroll
    for (int m = 0; m < 4; m++) {
        size_t r = (size_t)(r0 + ty * 4 + m);
#pragma unroll
        for (int n = 0; n < 8; n++) {
            int c = tx * 8 + n;
            float v = 1.f / (1.f + expf(-(acc[m][n] + g_bg[c])));
            if (c < 64) {
                float rh = v * hx[r * 64 + c];
                g_rh[r * 64 + c] = rh;
                g_rhh[r * 64 + c] = __float2bfloat16_rn(rh);
            } else {
                g_u[r * 64 + (c - 64)] = v;
            }
        }
    }
}

// ---------------- final: c = tanh(X2eff @ Wc^T + bc); out = u*h + (1-u)*c ----------------
__global__ __launch_bounds__(256) void final_kernel(const float* __restrict__ inputs,
                                                    const float* __restrict__ hx,
                                                    float* __restrict__ out) {
    constexpr int KT = 32;
    __shared__ float Xs[KT][64 + 4];
    __shared__ float Ws[KT][64 + 4];
    int r0 = blockIdx.x * 64;
    int t = threadIdx.x, ty = t >> 4, tx = t & 15;
    float acc[4][4];
#pragma unroll
    for (int m = 0; m < 4; m++)
#pragma unroll
        for (int n = 0; n < 4; n++) acc[m][n] = 0.f;

    for (int k0 = 0; k0 < 384; k0 += KT) {
        int reg = k0 >> 7;
#pragma unroll
        for (int p = 0; p < 2; p++) {
            int ii = (t >> 3) + p * 32;
            int kq = (t & 7) << 2;
            int r = r0 + ii;
            int f = (k0 + kq) & 127;
            float4 xv = (f < 64) ? *(const float4*)(inputs + (size_t)r * 64 + f)
                                 : *(const float4*)(g_rh + (size_t)r * 64 + (f - 64));
            if (reg == 1) {
                float4 y = (f < 64) ? *(const float4*)(g_Y0 + (size_t)r * 128 + f)
                                    : *(const float4*)(g_Y0p + (size_t)r * 64 + (f - 64));
                float di = 1.f / g_d0[r];
                xv.x = (xv.x + y.x) * di; xv.y = (xv.y + y.y) * di;
                xv.z = (xv.z + y.z) * di; xv.w = (xv.w + y.w) * di;
            } else if (reg == 2) {
                float4 y = (f < 64) ? *(const float4*)(g_Y1 + (size_t)r * 128 + f)
                                    : *(const float4*)(g_Y1p + (size_t)r * 64 + (f - 64));
                float di = 1.f / g_d1[r];
                xv.x = (xv.x + y.x) * di; xv.y = (xv.y + y.y) * di;
                xv.z = (xv.z + y.z) * di; xv.w = (xv.w + y.w) * di;
            }
            Xs[kq + 0][ii] = xv.x; Xs[kq + 1][ii] = xv.y;
            Xs[kq + 2][ii] = xv.z; Xs[kq + 3][ii] = xv.w;
        }
#pragma unroll
        for (int p = 0; p < 2; p++) {
            int c = (t >> 3) + p * 32;
            int kq = (t & 7) << 2;
            float4 wv = *(const float4*)(g_Wc + c * 384 + k0 + kq);
            Ws[kq + 0][c] = wv.x; Ws[kq + 1][c] = wv.y;
            Ws[kq + 2][c] = wv.z; Ws[kq + 3][c] = wv.w;
        }
        __syncthreads();
#pragma unroll
        for (int kk = 0; kk < KT; kk++) {
            float a[4], wv[4];
#pragma unroll
            for (int m = 0; m < 4; m++) a[m] = Xs[kk][ty * 4 + m];
#pragma unroll
            for (int n = 0; n < 4; n++) wv[n] = Ws[kk][tx * 4 + n];
#pragma unroll
            for (int m = 0; m < 4; m++)
#pragma unroll
                for (int n = 0; n < 4; n++) acc[m][n] = fmaf(a[m], wv[n], acc[m][n]);
        }
        __syncthreads();
    }
#pragma unroll
    for (int m = 0; m < 4; m++) {
        size_t r = (size_t)(r0 + ty * 4 + m);
#pragma unroll
        for (int n = 0; n < 4; n++) {
            int c = tx * 4 + n;
            float cv = tanhf(acc[m][n] + g_bc[c]);
            float u = g_u[r * 64 + c];
            float h = hx[r * 64 + c];
            out[r * 64 + c] = u * h + (1.f - u) * cv;
        }
    }
}

// ---------------- launch ----------------
extern "C" void kernel_launch(void* const* d_in, const int* in_sizes, int n_in,
                              void* d_out, int out_size) {
    const float* logits = (const float*)d_in[0];
    const float* unoise = (const float*)d_in[1];
    const float* inputs = (const float*)d_in[2];
    const float* hx     = (const float*)d_in[3];
    const float* W0  = (const float*)d_in[4];
    const float* b0  = (const float*)d_in[5];
    const float* W1  = (const float*)d_in[6];
    const float* b1  = (const float*)d_in[7];
    const float* Wc0 = (const float*)d_in[8];
    const float* bc0 = (const float*)d_in[9];
    const float* Wc1 = (const float*)d_in[10];
    const float* bc1 = (const float*)d_in[11];
    float* out = (float*)d_out;

    static bool attr_done = false;
    if (!attr_done) {
        cudaFuncSetAttribute(adj_gemm_bf16<false, 0>, cudaFuncAttributeMaxDynamicSharedMemorySize, 65536);
        cudaFuncSetAttribute(adj_gemm_bf16<true, 0>,  cudaFuncAttributeMaxDynamicSharedMemorySize, 65536);
        cudaFuncSetAttribute(adj_gemm_bf16<false, 1>, cudaFuncAttributeMaxDynamicSharedMemorySize, 49152);
        cudaFuncSetAttribute(adj_gemm_bf16<true, 1>,  cudaFuncAttributeMaxDynamicSharedMemorySize, 49152);
        attr_done = true;
    }

    prep_kernel<<<48, 256>>>(W0, b0, W1, b1, Wc0, bc0, Wc1, bc1);
    convert_x_kernel<<<2048, 256>>>(inputs, hx);
    gumbel_kernel<<<dim3(32, BB), 256>>>(logits, unoise);
    colsum_kernel<<<dim3(8, BB), 256>>>();
    adj_gemm_bf16<false, 0><<<dim3(8, BB), 256, 65536>>>();
    adj_gemm_bf16<true, 0><<<dim3(8, BB), 256, 65536>>>();
    gate_kernel<<<256, 256>>>(inputs, hx);
    adj_gemm_bf16<false, 1><<<dim3(8, BB), 256, 49152>>>();
    adj_gemm_bf16<true, 1><<<dim3(8, BB), 256, 49152>>>();
    final_kernel<<<256, 256>>>(inputs, hx, out);
}

// round 7
// speedup vs baseline: 2.4436x; 1.0451x over previous
#include <cuda_runtime.h>
#include <cuda_bf16.h>
#include <cstdint>
#include <cstddef>

#define BB 16
#define NN 1024

// ---------------- device scratch ----------------
__device__ __nv_bfloat16 g_adjh[(size_t)BB * NN * NN];   // 32 MB adjacency (bf16)
__device__ float g_d0[BB * NN];                          // colsum+1
__device__ float g_d1[BB * NN];                          // rowsum+1
__device__ float g_cpart[(size_t)BB * 32 * NN];          // per-block column partials
__device__ float g_Y0[(size_t)BB * NN * 128];
__device__ float g_Y1[(size_t)BB * NN * 128];
__device__ float g_Y0p[(size_t)BB * NN * 64];
__device__ float g_Y1p[(size_t)BB * NN * 64];
__device__ float g_u[(size_t)BB * NN * 64];
__device__ float g_rh[(size_t)BB * NN * 64];             // fp32 r*h (for final region0)
__device__ __nv_bfloat16 g_xh[(size_t)BB * NN * 128];    // bf16 [inputs|hx]
__device__ __nv_bfloat16 g_rhh[(size_t)BB * NN * 64];    // bf16 r*h (GEMM operand)
__device__ float g_Wg[128 * 384];
__device__ float g_Wc[64 * 384];
__device__ float g_bg[128];
__device__ float g_bc[64];

// ---------------- PTX helpers ----------------
__device__ __forceinline__ void mma_bf16(float* c, uint32_t a0, uint32_t a1, uint32_t a2,
                                         uint32_t a3, uint32_t b0, uint32_t b1) {
    asm volatile(
        "mma.sync.aligned.m16n8k16.row.col.f32.bf16.bf16.f32 "
        "{%0,%1,%2,%3},{%4,%5,%6,%7},{%8,%9},{%0,%1,%2,%3};"
        : "+f"(c[0]), "+f"(c[1]), "+f"(c[2]), "+f"(c[3])
        : "r"(a0), "r"(a1), "r"(a2), "r"(a3), "r"(b0), "r"(b1));
}
__device__ __forceinline__ void ldsm4(uint32_t& r0, uint32_t& r1, uint32_t& r2, uint32_t& r3,
                                      uint32_t a) {
    asm volatile("ldmatrix.sync.aligned.m8n8.x4.shared.b16 {%0,%1,%2,%3},[%4];"
                 : "=r"(r0), "=r"(r1), "=r"(r2), "=r"(r3) : "r"(a));
}
__device__ __forceinline__ void ldsm4t(uint32_t& r0, uint32_t& r1, uint32_t& r2, uint32_t& r3,
                                       uint32_t a) {
    asm volatile("ldmatrix.sync.aligned.m8n8.x4.trans.shared.b16 {%0,%1,%2,%3},[%4];"
                 : "=r"(r0), "=r"(r1), "=r"(r2), "=r"(r3) : "r"(a));
}
__device__ __forceinline__ void cpasync16(uint32_t s, const void* g) {
    asm volatile("cp.async.cg.shared.global [%0],[%1],16;" :: "r"(s), "l"(g));
}
#define CP_COMMIT() asm volatile("cp.async.commit_group;")
#define CP_WAIT(n) asm volatile("cp.async.wait_group %0;" :: "n"(n))

// ---------------- prep: effective weights ----------------
// diffusion stack for K=2 is [x, Ax, Ax]: w_x[f] = W[c,3f], w_m[f] = W[c,3f+1]+W[c,3f+2]
__global__ void prep_kernel(const float* __restrict__ W0, const float* __restrict__ b0,
                            const float* __restrict__ W1, const float* __restrict__ b1,
                            const float* __restrict__ Wc0, const float* __restrict__ bc0,
                            const float* __restrict__ Wc1, const float* __restrict__ bc1) {
    int stride = gridDim.x * blockDim.x;
    int t0 = blockIdx.x * blockDim.x + threadIdx.x;
    for (int idx = t0; idx < 128 * 384; idx += stride) {
        int c = idx / 384, k = idx % 384;
        int reg = k >> 7, f = k & 127;
        float w;
        if (reg == 0)      w = W0[c * 384 + 3 * f]     + W1[c * 384 + 3 * f];
        else if (reg == 1) w = W0[c * 384 + 3 * f + 1] + W0[c * 384 + 3 * f + 2];
        else               w = W1[c * 384 + 3 * f + 1] + W1[c * 384 + 3 * f + 2];
        g_Wg[idx] = w;
    }
    for (int idx = t0; idx < 64 * 384; idx += stride) {
        int c = idx / 384, k = idx % 384;
        int reg = k >> 7, f = k & 127;
        float w;
        if (reg == 0)      w = Wc0[c * 384 + 3 * f]     + Wc1[c * 384 + 3 * f];
        else if (reg == 1) w = Wc0[c * 384 + 3 * f + 1] + Wc0[c * 384 + 3 * f + 2];
        else               w = Wc1[c * 384 + 3 * f + 1] + Wc1[c * 384 + 3 * f + 2];
        g_Wc[idx] = w;
    }
    if (t0 < 128) g_bg[t0] = b0[t0] + b1[t0];
    if (t0 < 64)  g_bc[t0] = bc0[t0] + bc1[t0];
}

// ---------------- convert [inputs|hx] -> bf16 g_xh ----------------
__global__ void convert_x_kernel(const float* __restrict__ inputs, const float* __restrict__ hx) {
    size_t idx = (size_t)blockIdx.x * blockDim.x + threadIdx.x;   // one float4 group
    if (idx >= (size_t)BB * NN * 32) return;
    size_t r = idx >> 5;
    int g = (int)(idx & 31);
    float4 v = (g < 16) ? *(const float4*)(inputs + r * 64 + g * 4)
                        : *(const float4*)(hx + r * 64 + (g - 16) * 4);
    __nv_bfloat162* dst = (__nv_bfloat162*)(g_xh + r * 128 + g * 4);
    dst[0] = __floats2bfloat162_rn(v.x, v.y);
    dst[1] = __floats2bfloat162_rn(v.z, v.w);
}

// ---------------- gumbel softmax -> bf16 adj + row sums + column partials ----------------
// Each thread covers a fixed set of 4 columns across all 32 rows of this block, so
// column partial sums accumulate in registers for free; written to g_cpart, reduced later.
__global__ void gumbel_kernel(const float* __restrict__ logits, const float* __restrict__ unoise) {
    int b = blockIdx.y;
    int i0 = blockIdx.x * 32;
    int t = threadIdx.x;
    int lane = t & 31, w = t >> 5;
    __shared__ float ws[32][8];
    const float4* lg = (const float4*)(logits + (size_t)b * NN * NN * 2);
    const float4* un = (const float4*)(unoise + (size_t)b * NN * NN * 2);
    __nv_bfloat162* adj2 = (__nv_bfloat162*)g_adjh + (size_t)b * NN * 512;
    float cs0 = 0.f, cs1 = 0.f, cs2 = 0.f, cs3 = 0.f;
    for (int ii = 0; ii < 32; ii++) {
        size_t base4 = (size_t)(i0 + ii) * 512;   // 512 bf162 per row
        float rp = 0.f;
        {
            int jp = t;
            float4 L = lg[base4 + jp];
            float4 Uv = un[base4 + jp];
            float n0 = -__logf(1e-10f - __logf(Uv.x + 1e-10f));
            float n1 = -__logf(1e-10f - __logf(Uv.y + 1e-10f));
            float n2 = -__logf(1e-10f - __logf(Uv.z + 1e-10f));
            float n3 = -__logf(1e-10f - __logf(Uv.w + 1e-10f));
            float z0 = (L.x + n0) - (L.y + n1);
            float z1 = (L.z + n2) - (L.w + n3);
            float a0 = 1.f / (1.f + __expf(-2.f * z0));
            float a1 = 1.f / (1.f + __expf(-2.f * z1));
            adj2[base4 + jp] = __floats2bfloat162_rn(a0, a1);
            rp += a0 + a1;
            cs0 += a0; cs1 += a1;
        }
        {
            int jp = t + 256;
            float4 L = lg[base4 + jp];
            float4 Uv = un[base4 + jp];
            float n0 = -__logf(1e-10f - __logf(Uv.x + 1e-10f));
            float n1 = -__logf(1e-10f - __logf(Uv.y + 1e-10f));
            float n2 = -__logf(1e-10f - __logf(Uv.z + 1e-10f));
            float n3 = -__logf(1e-10f - __logf(Uv.w + 1e-10f));
            float z0 = (L.x + n0) - (L.y + n1);
            float z1 = (L.z + n2) - (L.w + n3);
            float a0 = 1.f / (1.f + __expf(-2.f * z0));
            float a1 = 1.f / (1.f + __expf(-2.f * z1));
            adj2[base4 + jp] = __floats2bfloat162_rn(a0, a1);
            rp += a0 + a1;
            cs2 += a0; cs3 += a1;
        }
#pragma unroll
        for (int off = 16; off; off >>= 1) rp += __shfl_down_sync(0xffffffffu, rp, off);
        if (lane == 0) ws[ii][w] = rp;
    }
    // column partials: thread t owns columns 2t, 2t+1, 2t+512, 2t+513
    float* cp = g_cpart + ((size_t)b * 32 + blockIdx.x) * NN;
    *(float2*)(cp + 2 * t) = make_float2(cs0, cs1);
    *(float2*)(cp + 2 * t + 512) = make_float2(cs2, cs3);
    __syncthreads();
    if (t < 32) {
        float s = 0.f;
#pragma unroll
        for (int q = 0; q < 8; q++) s += ws[t][q];
        g_d1[b * NN + i0 + t] = s + 1.0f;
    }
}

// ---------------- d0 = sum of 32 column partials + 1 ----------------
__global__ void d0_reduce_kernel() {
    int idx = blockIdx.x * 256 + threadIdx.x;   // 16384 total
    int b = idx >> 10, c = idx & 1023;
    const float* cp = g_cpart + (size_t)b * 32 * NN + c;
    float s = 0.f;
#pragma unroll
    for (int i = 0; i < 32; i++) s += cp[(size_t)i * NN];
    g_d0[b * NN + c] = s + 1.0f;
}

// ---------------- adjacency GEMM: bf16 mma + ldmatrix + cp.async double-buffer ----------
// C[b,i,c] = sum_k Aeff[i,k] * X[k,c];  Aeff = adj (trans: adjT), trans = blockIdx.z.
// Both orientations in ONE launch (2*BB*8 = 256 CTAs) to fill the 148 SMs.
// CTA 128m x NC, 256 threads = 8 warps (4m x 2n), K-tile 64, XOR-swizzled tiles,
// ldmatrix(.trans) fragments, 2-stage cp.async pipeline.
// PASS=0: NC=128, X=g_xh, out g_Y0/g_Y1. PASS=1: NC=64, X=g_rhh, out g_Y0p/g_Y1p.
template <int PASS>
__global__ __launch_bounds__(256) void adj_gemm_bf16() {
    constexpr int NC = (PASS == 0) ? 128 : 64;
    constexpr int NT = NC / 16;
    constexpr int BS_STAGE = 64 * NC * 2;
    extern __shared__ __nv_bfloat16 smem[];
    __nv_bfloat16* As = smem;
    __nv_bfloat16* Bsh = smem + 2 * 128 * 64;
    const bool trans = (blockIdx.z != 0);
    int b = blockIdx.y;
    int i0 = blockIdx.x * 128;
    const __nv_bfloat16* adj = g_adjh + (size_t)b * NN * NN;
    const __nv_bfloat16* Bsrc = ((PASS == 0) ? g_xh : g_rhh) + (size_t)b * NN * NC;
    int t = threadIdx.x, lane = t & 31, wid = t >> 5;
    int wm = wid >> 1, wn = wid & 1;
    uint32_t as_base = (uint32_t)__cvta_generic_to_shared(As);
    uint32_t bs_base = (uint32_t)__cvta_generic_to_shared(Bsh);

    float acc[2][NT][4];
#pragma unroll
    for (int mt = 0; mt < 2; mt++)
#pragma unroll
        for (int nt = 0; nt < NT; nt++)
#pragma unroll
            for (int q = 0; q < 4; q++) acc[mt][nt][q] = 0.f;

    auto fill = [&](int st, int k0) {
#pragma unroll
        for (int it = 0; it < 4; it++) {
            int q = t + it * 256;
            if (!trans) {
                int m = q >> 3, cc = q & 7;
                uint32_t dst = as_base + st * 16384 + (((m << 3) + (cc ^ (m & 7))) << 4);
                cpasync16(dst, adj + (size_t)(i0 + m) * NN + k0 + cc * 8);
            } else {
                int k = q >> 4, cc = q & 15;
                uint32_t dst = as_base + st * 16384 + (((k << 4) + (cc ^ (k & 7))) << 4);
                cpasync16(dst, adj + (size_t)(k0 + k) * NN + i0 + cc * 8);
            }
        }
        if (PASS == 0) {
#pragma unroll
            for (int it = 0; it < 4; it++) {
                int q = t + it * 256;
                int k = q >> 4, cc = q & 15;
                uint32_t dst = bs_base + st * BS_STAGE + (((k << 4) + (cc ^ (k & 7))) << 4);
                cpasync16(dst, Bsrc + (size_t)(k0 + k) * 128 + cc * 8);
            }
        } else {
#pragma unroll
            for (int it = 0; it < 2; it++) {
                int q = t + it * 256;
                int k = q >> 3, cc = q & 7;
                uint32_t dst = bs_base + st * BS_STAGE + (((k << 3) + (cc ^ (k & 7))) << 4);
                cpasync16(dst, Bsrc + (size_t)(k0 + k) * 64 + cc * 8);
            }
        }
    };

    fill(0, 0);
    CP_COMMIT();
    for (int kt = 0; kt < 16; kt++) {
        int st = kt & 1;
        if (kt + 1 < 16) {
            fill(st ^ 1, (kt + 1) * 64);
            CP_COMMIT();
            CP_WAIT(1);
        } else {
            CP_WAIT(0);
        }
        __syncthreads();
#pragma unroll
        for (int kk = 0; kk < 4; kk++) {
            uint32_t Af[2][4];
#pragma unroll
            for (int mt = 0; mt < 2; mt++) {
                if (!trans) {
                    int r = wm * 32 + mt * 16 + (lane & 15);
                    int cc = (kk << 1) + (lane >> 4);
                    uint32_t a = as_base + st * 16384 + (((r << 3) + (cc ^ (r & 7))) << 4);
                    ldsm4(Af[mt][0], Af[mt][1], Af[mt][2], Af[mt][3], a);
                } else {
                    int r = (kk << 4) + (lane & 15);
                    int cc = ((wm * 32 + mt * 16) >> 3) + (lane >> 4);
                    uint32_t a = as_base + st * 16384 + (((r << 4) + (cc ^ (r & 7))) << 4);
                    uint32_t p0, p1, p2, p3;
                    ldsm4t(p0, p1, p2, p3, a);
                    Af[mt][0] = p0; Af[mt][1] = p2; Af[mt][2] = p1; Af[mt][3] = p3;
                }
            }
            uint32_t Bf[NT][2];
#pragma unroll
            for (int np = 0; np < NT / 2; np++) {
                int r = (kk << 4) + (lane & 15);
                int cc = ((wn * (NC / 2) + np * 16) >> 3) + (lane >> 4);
                uint32_t a = bs_base + st * BS_STAGE + ((r * (NC / 8) + (cc ^ (r & 7))) << 4);
                uint32_t q0, q1, q2, q3;
                ldsm4t(q0, q1, q2, q3, a);
                Bf[2 * np][0] = q0; Bf[2 * np][1] = q1;
                Bf[2 * np + 1][0] = q2; Bf[2 * np + 1][1] = q3;
            }
#pragma unroll
            for (int mt = 0; mt < 2; mt++)
#pragma unroll
                for (int nt = 0; nt < NT; nt++)
                    mma_bf16(acc[mt][nt], Af[mt][0], Af[mt][1], Af[mt][2], Af[mt][3],
                             Bf[nt][0], Bf[nt][1]);
        }
        __syncthreads();
    }

    float* out = (PASS == 0) ? (trans ? g_Y1 : g_Y0) : (trans ? g_Y1p : g_Y0p);
    int g = lane >> 2, tt = lane & 3;
#pragma unroll
    for (int mt = 0; mt < 2; mt++) {
#pragma unroll
        for (int nt = 0; nt < NT; nt++) {
            int row = i0 + wm * 32 + mt * 16 + g;
            int col = wn * (NC / 2) + nt * 8 + 2 * tt;
            *(float2*)(out + ((size_t)b * NN + row) * NC + col) =
                make_float2(acc[mt][nt][0], acc[mt][nt][1]);
            *(float2*)(out + ((size_t)b * NN + row + 8) * NC + col) =
                make_float2(acc[mt][nt][2], acc[mt][nt][3]);
        }
    }
}

// ---------------- gate: value = sigmoid(Xeff @ Wg^T + bg); emit u, r*h (fp32+bf16) ------
__global__ __launch_bounds__(256) void gate_kernel(const float* __restrict__ inputs,
                                                   const float* __restrict__ hx) {
    constexpr int KT = 32;
    __shared__ float Xs[KT][64 + 4];
    __shared__ float Ws[KT][128 + 4];
    int r0 = blockIdx.x * 64;
    int t = threadIdx.x, ty = t >> 4, tx = t & 15;
    float acc[4][8];
#pragma unroll
    for (int m = 0; m < 4; m++)
#pragma unroll
        for (int n = 0; n < 8; n++) acc[m][n] = 0.f;

    for (int k0 = 0; k0 < 384; k0 += KT) {
        int reg = k0 >> 7;
#pragma unroll
        for (int p = 0; p < 2; p++) {
            int ii = (t >> 3) + p * 32;
            int kq = (t & 7) << 2;
            int r = r0 + ii;
            int f = (k0 + kq) & 127;
            float4 xv = (f < 64) ? *(const float4*)(inputs + (size_t)r * 64 + f)
                                 : *(const float4*)(hx + (size_t)r * 64 + (f - 64));
            if (reg == 1) {
                float4 y = *(const float4*)(g_Y0 + (size_t)r * 128 + f);
                float di = 1.f / g_d0[r];
                xv.x = (xv.x + y.x) * di; xv.y = (xv.y + y.y) * di;
                xv.z = (xv.z + y.z) * di; xv.w = (xv.w + y.w) * di;
            } else if (reg == 2) {
                float4 y = *(const float4*)(g_Y1 + (size_t)r * 128 + f);
                float di = 1.f / g_d1[r];
                xv.x = (xv.x + y.x) * di; xv.y = (xv.y + y.y) * di;
                xv.z = (xv.z + y.z) * di; xv.w = (xv.w + y.w) * di;
            }
            Xs[kq + 0][ii] = xv.x; Xs[kq + 1][ii] = xv.y;
            Xs[kq + 2][ii] = xv.z; Xs[kq + 3][ii] = xv.w;
        }
#pragma unroll
        for (int p = 0; p < 4; p++) {
            int c = (t >> 3) + p * 32;
            int kq = (t & 7) << 2;
            float4 wv = *(const float4*)(g_Wg + c * 384 + k0 + kq);
            Ws[kq + 0][c] = wv.x; Ws[kq + 1][c] = wv.y;
            Ws[kq + 2][c] = wv.z; Ws[kq + 3][c] = wv.w;
        }
        __syncthreads();
#pragma unroll
        for (int kk = 0; kk < KT; kk++) {
            float a[4], wv[8];
#pragma unroll
            for (int m = 0; m < 4; m++) a[m] = Xs[kk][ty * 4 + m];
#pragma unroll
            for (int n = 0; n < 8; n++) wv[n] = Ws[kk][tx * 8 + n];
#pragma unroll
            for (int m = 0; m < 4; m++)
#pragma unroll
                for (int n = 0; n < 8; n++) acc[m][n] = fmaf(a[m], wv[n], acc[m][n]);
        }
        __syncthreads();
    }
#pragma unroll
    for (int m = 0; m < 4; m++) {
        size_t r = (size_t)(r0 + ty * 4 + m);
#pragma unroll
        for (int n = 0; n < 8; n++) {
            int c = tx * 8 + n;
            float v = 1.f / (1.f + expf(-(acc[m][n] + g_bg[c])));
            if (c < 64) {
                float rh = v * hx[r * 64 + c];
                g_rh[r * 64 + c] = rh;
                g_rhh[r * 64 + c] = __float2bfloat16_rn(rh);
            } else {
                g_u[r * 64 + (c - 64)] = v;
            }
        }
    }
}

// ---------------- final: c = tanh(X2eff @ Wc^T + bc); out = u*h + (1-u)*c ----------------
__global__ __launch_bounds__(256) void final_kernel(const float* __restrict__ inputs,
                                                    const float* __restrict__ hx,
                                                    float* __restrict__ out) {
    constexpr int KT = 32;
    __shared__ float Xs[KT][64 + 4];
    __shared__ float Ws[KT][64 + 4];
    int r0 = blockIdx.x * 64;
    int t = threadIdx.x, ty = t >> 4, tx = t & 15;
    float acc[4][4];
#pragma unroll
    for (int m = 0; m < 4; m++)
#pragma unroll
        for (int n = 0; n < 4; n++) acc[m][n] = 0.f;

    for (int k0 = 0; k0 < 384; k0 += KT) {
        int reg = k0 >> 7;
#pragma unroll
        for (int p = 0; p < 2; p++) {
            int ii = (t >> 3) + p * 32;
            int kq = (t & 7) << 2;
            int r = r0 + ii;
            int f = (k0 + kq) & 127;
            float4 xv = (f < 64) ? *(const float4*)(inputs + (size_t)r * 64 + f)
                                 : *(const float4*)(g_rh + (size_t)r * 64 + (f - 64));
            if (reg == 1) {
                float4 y = (f < 64) ? *(const float4*)(g_Y0 + (size_t)r * 128 + f)
                                    : *(const float4*)(g_Y0p + (size_t)r * 64 + (f - 64));
                float di = 1.f / g_d0[r];
                xv.x = (xv.x + y.x) * di; xv.y = (xv.y + y.y) * di;
                xv.z = (xv.z + y.z) * di; xv.w = (xv.w + y.w) * di;
            } else if (reg == 2) {
                float4 y = (f < 64) ? *(const float4*)(g_Y1 + (size_t)r * 128 + f)
                                    : *(const float4*)(g_Y1p + (size_t)r * 64 + (f - 64));
                float di = 1.f / g_d1[r];
                xv.x = (xv.x + y.x) * di; xv.y = (xv.y + y.y) * di;
                xv.z = (xv.z + y.z) * di; xv.w = (xv.w + y.w) * di;
            }
            Xs[kq + 0][ii] = xv.x; Xs[kq + 1][ii] = xv.y;
            Xs[kq + 2][ii] = xv.z; Xs[kq + 3][ii] = xv.w;
        }
#pragma unroll
        for (int p = 0; p < 2; p++) {
            int c = (t >> 3) + p * 32;
            int kq = (t & 7) << 2;
            float4 wv = *(const float4*)(g_Wc + c * 384 + k0 + kq);
            Ws[kq + 0][c] = wv.x; Ws[kq + 1][c] = wv.y;
            Ws[kq + 2][c] = wv.z; Ws[kq + 3][c] = wv.w;
        }
        __syncthreads();
#pragma unroll
        for (int kk = 0; kk < KT; kk++) {
            float a[4], wv[4];
#pragma unroll
            for (int m = 0; m < 4; m++) a[m] = Xs[kk][ty * 4 + m];
#pragma unroll
            for (int n = 0; n < 4; n++) wv[n] = Ws[kk][tx * 4 + n];
#pragma unroll
            for (int m = 0; m < 4; m++)
#pragma unroll
                for (int n = 0; n < 4; n++) acc[m][n] = fmaf(a[m], wv[n], acc[m][n]);
        }
        __syncthreads();
    }
#pragma unroll
    for (int m = 0; m < 4; m++) {
        size_t r = (size_t)(r0 + ty * 4 + m);
#pragma unroll
        for (int n = 0; n < 4; n++) {
            int c = tx * 4 + n;
            float cv = tanhf(acc[m][n] + g_bc[c]);
            float u = g_u[r * 64 + c];
            float h = hx[r * 64 + c];
            out[r * 64 + c] = u * h + (1.f - u) * cv;
        }
    }
}

// ---------------- launch ----------------
extern "C" void kernel_launch(void* const* d_in, const int* in_sizes, int n_in,
                              void* d_out, int out_size) {
    const float* logits = (const float*)d_in[0];
    const float* unoise = (const float*)d_in[1];
    const float* inputs = (const float*)d_in[2];
    const float* hx     = (const float*)d_in[3];
    const float* W0  = (const float*)d_in[4];
    const float* b0  = (const float*)d_in[5];
    const float* W1  = (const float*)d_in[6];
    const float* b1  = (const float*)d_in[7];
    const float* Wc0 = (const float*)d_in[8];
    const float* bc0 = (const float*)d_in[9];
    const float* Wc1 = (const float*)d_in[10];
    const float* bc1 = (const float*)d_in[11];
    float* out = (float*)d_out;

    static bool attr_done = false;
    if (!attr_done) {
        cudaFuncSetAttribute(adj_gemm_bf16<0>, cudaFuncAttributeMaxDynamicSharedMemorySize, 65536);
        cudaFuncSetAttribute(adj_gemm_bf16<1>, cudaFuncAttributeMaxDynamicSharedMemorySize, 49152);
        attr_done = true;
    }

    prep_kernel<<<48, 256>>>(W0, b0, W1, b1, Wc0, bc0, Wc1, bc1);
    convert_x_kernel<<<2048, 256>>>(inputs, hx);
    gumbel_kernel<<<dim3(32, BB), 256>>>(logits, unoise);
    d0_reduce_kernel<<<64, 256>>>();
    adj_gemm_bf16<0><<<dim3(8, BB, 2), 256, 65536>>>();
    gate_kernel<<<256, 256>>>(inputs, hx);
    adj_gemm_bf16<1><<<dim3(8, BB, 2), 256, 49152>>>();
    final_kernel<<<256, 256>>>(inputs, hx, out);
}

// round 9
// speedup vs baseline: 2.5000x; 1.0231x over previous
#include <cuda_runtime.h>
#include <cuda_bf16.h>
#include <cstdint>
#include <cstddef>

#define BB 16
#define NN 1024

// ---------------- device scratch ----------------
__device__ __nv_bfloat16 g_adjh[(size_t)BB * NN * NN];   // 32 MB adjacency (bf16)
__device__ float g_d0[BB * NN];                          // colsum+1 (written by gate)
__device__ float g_d1[BB * NN];                          // rowsum+1 (written by gumbel)
__device__ float g_cpart[(size_t)BB * 64 * NN];          // per-block column partials (64 blocks)
__device__ __nv_bfloat16 g_Y0h[(size_t)BB * NN * 128];   // adj  @ [x,h]  (bf16)
__device__ __nv_bfloat16 g_Y1h[(size_t)BB * NN * 128];   // adjT @ [x,h]  (bf16)
__device__ __nv_bfloat16 g_Y0ph[(size_t)BB * NN * 64];   // adj  @ (r*h)  (bf16)
__device__ __nv_bfloat16 g_Y1ph[(size_t)BB * NN * 64];   // adjT @ (r*h)  (bf16)
__device__ float g_u[(size_t)BB * NN * 64];
__device__ float g_rh[(size_t)BB * NN * 64];             // fp32 r*h (final region0)
__device__ __nv_bfloat16 g_xh[(size_t)BB * NN * 128];    // bf16 [inputs|hx]
__device__ __nv_bfloat16 g_rhh[(size_t)BB * NN * 64];    // bf16 r*h (GEMM operand)
__device__ float g_Wg[128 * 384];
__device__ float g_Wc[64 * 384];
__device__ float g_bg[128];
__device__ float g_bc[64];

// ---------------- PTX helpers ----------------
__device__ __forceinline__ void mma_bf16(float* c, uint32_t a0, uint32_t a1, uint32_t a2,
                                         uint32_t a3, uint32_t b0, uint32_t b1) {
    asm volatile(
        "mma.sync.aligned.m16n8k16.row.col.f32.bf16.bf16.f32 "
        "{%0,%1,%2,%3},{%4,%5,%6,%7},{%8,%9},{%0,%1,%2,%3};"
        : "+f"(c[0]), "+f"(c[1]), "+f"(c[2]), "+f"(c[3])
        : "r"(a0), "r"(a1), "r"(a2), "r"(a3), "r"(b0), "r"(b1));
}
__device__ __forceinline__ void ldsm4(uint32_t& r0, uint32_t& r1, uint32_t& r2, uint32_t& r3,
                                      uint32_t a) {
    asm volatile("ldmatrix.sync.aligned.m8n8.x4.shared.b16 {%0,%1,%2,%3},[%4];"
                 : "=r"(r0), "=r"(r1), "=r"(r2), "=r"(r3) : "r"(a));
}
__device__ __forceinline__ void ldsm4t(uint32_t& r0, uint32_t& r1, uint32_t& r2, uint32_t& r3,
                                       uint32_t a) {
    asm volatile("ldmatrix.sync.aligned.m8n8.x4.trans.shared.b16 {%0,%1,%2,%3},[%4];"
                 : "=r"(r0), "=r"(r1), "=r"(r2), "=r"(r3) : "r"(a));
}
__device__ __forceinline__ void cpasync16(uint32_t s, const void* g) {
    asm volatile("cp.async.cg.shared.global [%0],[%1],16;" :: "r"(s), "l"(g));
}
#define CP_COMMIT() asm volatile("cp.async.commit_group;")
#define CP_WAIT(n) asm volatile("cp.async.wait_group %0;" :: "n"(n))

// ---------------- prep (effective weights) + convert [inputs|hx]->bf16, one launch ------
// diffusion stack for K=2 is [x, Ax, Ax]: w_x[f] = W[c,3f], w_m[f] = W[c,3f+1]+W[c,3f+2]
__global__ void prep_convert_kernel(const float* __restrict__ inputs, const float* __restrict__ hx,
                                    const float* __restrict__ W0, const float* __restrict__ b0,
                                    const float* __restrict__ W1, const float* __restrict__ b1,
                                    const float* __restrict__ Wc0, const float* __restrict__ bc0,
                                    const float* __restrict__ Wc1, const float* __restrict__ bc1) {
    if (blockIdx.x < 2048) {
        size_t idx = (size_t)blockIdx.x * blockDim.x + threadIdx.x;   // one float4 group
        size_t r = idx >> 5;
        int g = (int)(idx & 31);
        float4 v = (g < 16) ? *(const float4*)(inputs + r * 64 + g * 4)
                            : *(const float4*)(hx + r * 64 + (g - 16) * 4);
        __nv_bfloat162* dst = (__nv_bfloat162*)(g_xh + r * 128 + g * 4);
        dst[0] = __floats2bfloat162_rn(v.x, v.y);
        dst[1] = __floats2bfloat162_rn(v.z, v.w);
        return;
    }
    int t0 = (blockIdx.x - 2048) * 256 + threadIdx.x;
    int stride = 48 * 256;
    for (int idx = t0; idx < 128 * 384; idx += stride) {
        int c = idx / 384, k = idx % 384;
        int reg = k >> 7, f = k & 127;
        float w;
        if (reg == 0)      w = W0[c * 384 + 3 * f]     + W1[c * 384 + 3 * f];
        else if (reg == 1) w = W0[c * 384 + 3 * f + 1] + W0[c * 384 + 3 * f + 2];
        else               w = W1[c * 384 + 3 * f + 1] + W1[c * 384 + 3 * f + 2];
        g_Wg[idx] = w;
    }
    for (int idx = t0; idx < 64 * 384; idx += stride) {
        int c = idx / 384, k = idx % 384;
        int reg = k >> 7, f = k & 127;
        float w;
        if (reg == 0)      w = Wc0[c * 384 + 3 * f]     + Wc1[c * 384 + 3 * f];
        else if (reg == 1) w = Wc0[c * 384 + 3 * f + 1] + Wc0[c * 384 + 3 * f + 2];
        else               w = Wc1[c * 384 + 3 * f + 1] + Wc1[c * 384 + 3 * f + 2];
        g_Wc[idx] = w;
    }
    if (t0 < 128) g_bg[t0] = b0[t0] + b1[t0];
    if (t0 < 64)  g_bc[t0] = bc0[t0] + bc1[t0];
}

// ---------------- gumbel softmax -> bf16 adj + row sums + column partials ----------------
// 16 rows per CTA (1024 CTAs). Each thread owns fixed columns 2t,2t+1,2t+512,2t+513 across
// its rows: column partials accumulate in registers, written to g_cpart (reduced in gate).
__global__ void gumbel_kernel(const float* __restrict__ logits, const float* __restrict__ unoise) {
    int b = blockIdx.y;
    int i0 = blockIdx.x * 16;
    int t = threadIdx.x;
    int lane = t & 31, w = t >> 5;
    __shared__ float ws[16][8];
    const float4* lg = (const float4*)(logits + (size_t)b * NN * NN * 2);
    const float4* un = (const float4*)(unoise + (size_t)b * NN * NN * 2);
    __nv_bfloat162* adj2 = (__nv_bfloat162*)g_adjh + (size_t)b * NN * 512;
    float cs0 = 0.f, cs1 = 0.f, cs2 = 0.f, cs3 = 0.f;
#pragma unroll 2
    for (int ii = 0; ii < 16; ii++) {
        size_t base4 = (size_t)(i0 + ii) * 512;   // 512 bf162 per row
        float rp = 0.f;
        {
            int jp = t;
            float4 L = lg[base4 + jp];
            float4 Uv = un[base4 + jp];
            float n0 = -__logf(1e-10f - __logf(Uv.x + 1e-10f));
            float n1 = -__logf(1e-10f - __logf(Uv.y + 1e-10f));
            float n2 = -__logf(1e-10f - __logf(Uv.z + 1e-10f));
            float n3 = -__logf(1e-10f - __logf(Uv.w + 1e-10f));
            float z0 = (L.x + n0) - (L.y + n1);
            float z1 = (L.z + n2) - (L.w + n3);
            float a0 = 1.f / (1.f + __expf(-2.f * z0));
            float a1 = 1.f / (1.f + __expf(-2.f * z1));
            adj2[base4 + jp] = __floats2bfloat162_rn(a0, a1);
            rp += a0 + a1;
            cs0 += a0; cs1 += a1;
        }
        {
            int jp = t + 256;
            float4 L = lg[base4 + jp];
            float4 Uv = un[base4 + jp];
            float n0 = -__logf(1e-10f - __logf(Uv.x + 1e-10f));
            float n1 = -__logf(1e-10f - __logf(Uv.y + 1e-10f));
            float n2 = -__logf(1e-10f - __logf(Uv.z + 1e-10f));
            float n3 = -__logf(1e-10f - __logf(Uv.w + 1e-10f));
            float z0 = (L.x + n0) - (L.y + n1);
            float z1 = (L.z + n2) - (L.w + n3);
            float a0 = 1.f / (1.f + __expf(-2.f * z0));
            float a1 = 1.f / (1.f + __expf(-2.f * z1));
            adj2[base4 + jp] = __floats2bfloat162_rn(a0, a1);
            rp += a0 + a1;
            cs2 += a0; cs3 += a1;
        }
#pragma unroll
        for (int off = 16; off; off >>= 1) rp += __shfl_down_sync(0xffffffffu, rp, off);
        if (lane == 0) ws[ii][w] = rp;
    }
    float* cp = g_cpart + ((size_t)b * 64 + blockIdx.x) * NN;
    *(float2*)(cp + 2 * t) = make_float2(cs0, cs1);
    *(float2*)(cp + 2 * t + 512) = make_float2(cs2, cs3);
    __syncthreads();
    if (t < 16) {
        float s = 0.f;
#pragma unroll
        for (int q = 0; q < 8; q++) s += ws[t][q];
        g_d1[b * NN + i0 + t] = s + 1.0f;
    }
}

// ---------------- adjacency GEMM: bf16 mma + ldmatrix + cp.async double-buffer ----------
// C[b,i,c] = sum_k Aeff[i,k] * X[k,c];  Aeff = adj (trans: adjT), trans = blockIdx.z.
// Both orientations in ONE launch. CTA 128m x NC, 256 threads = 8 warps (4m x 2n),
// K-tile 64, XOR-swizzled tiles, ldmatrix(.trans) fragments, 2-stage cp.async pipeline.
// Outputs bf16. PASS=0: NC=128, X=g_xh -> g_Y0h/g_Y1h. PASS=1: NC=64, X=g_rhh -> g_Y0ph/g_Y1ph.
template <int PASS>
__global__ __launch_bounds__(256) void adj_gemm_bf16() {
    constexpr int NC = (PASS == 0) ? 128 : 64;
    constexpr int NT = NC / 16;
    constexpr int BS_STAGE = 64 * NC * 2;
    extern __shared__ __nv_bfloat16 smem[];
    __nv_bfloat16* As = smem;
    __nv_bfloat16* Bsh = smem + 2 * 128 * 64;
    const bool trans = (blockIdx.z != 0);
    int b = blockIdx.y;
    int i0 = blockIdx.x * 128;
    const __nv_bfloat16* adj = g_adjh + (size_t)b * NN * NN;
    const __nv_bfloat16* Bsrc = ((PASS == 0) ? g_xh : g_rhh) + (size_t)b * NN * NC;
    int t = threadIdx.x, lane = t & 31, wid = t >> 5;
    int wm = wid >> 1, wn = wid & 1;
    uint32_t as_base = (uint32_t)__cvta_generic_to_shared(As);
    uint32_t bs_base = (uint32_t)__cvta_generic_to_shared(Bsh);

    float acc[2][NT][4];
#pragma unroll
    for (int mt = 0; mt < 2; mt++)
#pragma unroll
        for (int nt = 0; nt < NT; nt++)
#pragma unroll
            for (int q = 0; q < 4; q++) acc[mt][nt][q] = 0.f;

    auto fill = [&](int st, int k0) {
#pragma unroll
        for (int it = 0; it < 4; it++) {
            int q = t + it * 256;
            if (!trans) {
                int m = q >> 3, cc = q & 7;
                uint32_t dst = as_base + st * 16384 + (((m << 3) + (cc ^ (m & 7))) << 4);
                cpasync16(dst, adj + (size_t)(i0 + m) * NN + k0 + cc * 8);
            } else {
                int k = q >> 4, cc = q & 15;
                uint32_t dst = as_base + st * 16384 + (((k << 4) + (cc ^ (k & 7))) << 4);
                cpasync16(dst, adj + (size_t)(k0 + k) * NN + i0 + cc * 8);
            }
        }
        if (PASS == 0) {
#pragma unroll
            for (int it = 0; it < 4; it++) {
                int q = t + it * 256;
                int k = q >> 4, cc = q & 15;
                uint32_t dst = bs_base + st * BS_STAGE + (((k << 4) + (cc ^ (k & 7))) << 4);
                cpasync16(dst, Bsrc + (size_t)(k0 + k) * 128 + cc * 8);
            }
        } else {
#pragma unroll
            for (int it = 0; it < 2; it++) {
                int q = t + it * 256;
                int k = q >> 3, cc = q & 7;
                uint32_t dst = bs_base + st * BS_STAGE + (((k << 3) + (cc ^ (k & 7))) << 4);
                cpasync16(dst, Bsrc + (size_t)(k0 + k) * 64 + cc * 8);
            }
        }
    };

    fill(0, 0);
    CP_COMMIT();
    for (int kt = 0; kt < 16; kt++) {
        int st = kt & 1;
        if (kt + 1 < 16) {
            fill(st ^ 1, (kt + 1) * 64);
            CP_COMMIT();
            CP_WAIT(1);
        } else {
            CP_WAIT(0);
        }
        __syncthreads();
#pragma unroll
        for (int kk = 0; kk < 4; kk++) {
            uint32_t Af[2][4];
#pragma unroll
            for (int mt = 0; mt < 2; mt++) {
                if (!trans) {
                    int r = wm * 32 + mt * 16 + (lane & 15);
                    int cc = (kk << 1) + (lane >> 4);
                    uint32_t a = as_base + st * 16384 + (((r << 3) + (cc ^ (r & 7))) << 4);
                    ldsm4(Af[mt][0], Af[mt][1], Af[mt][2], Af[mt][3], a);
                } else {
                    int r = (kk << 4) + (lane & 15);
                    int cc = ((wm * 32 + mt * 16) >> 3) + (lane >> 4);
                    uint32_t a = as_base + st * 16384 + (((r << 4) + (cc ^ (r & 7))) << 4);
                    uint32_t p0, p1, p2, p3;
                    ldsm4t(p0, p1, p2, p3, a);
                    Af[mt][0] = p0; Af[mt][1] = p2; Af[mt][2] = p1; Af[mt][3] = p3;
                }
            }
            uint32_t Bf[NT][2];
#pragma unroll
            for (int np = 0; np < NT / 2; np++) {
                int r = (kk << 4) + (lane & 15);
                int cc = ((wn * (NC / 2) + np * 16) >> 3) + (lane >> 4);
                uint32_t a = bs_base + st * BS_STAGE + ((r * (NC / 8) + (cc ^ (r & 7))) << 4);
                uint32_t q0, q1, q2, q3;
                ldsm4t(q0, q1, q2, q3, a);
                Bf[2 * np][0] = q0; Bf[2 * np][1] = q1;
                Bf[2 * np + 1][0] = q2; Bf[2 * np + 1][1] = q3;
            }
#pragma unroll
            for (int mt = 0; mt < 2; mt++)
#pragma unroll
                for (int nt = 0; nt < NT; nt++)
                    mma_bf16(acc[mt][nt], Af[mt][0], Af[mt][1], Af[mt][2], Af[mt][3],
                             Bf[nt][0], Bf[nt][1]);
        }
        __syncthreads();
    }

    __nv_bfloat16* out = (PASS == 0) ? (trans ? g_Y1h : g_Y0h) : (trans ? g_Y1ph : g_Y0ph);
    int g = lane >> 2, tt = lane & 3;
#pragma unroll
    for (int mt = 0; mt < 2; mt++) {
#pragma unroll
        for (int nt = 0; nt < NT; nt++) {
            int row = i0 + wm * 32 + mt * 16 + g;
            int col = wn * (NC / 2) + nt * 8 + 2 * tt;
            *(__nv_bfloat162*)(out + ((size_t)b * NN + row) * NC + col) =
                __floats2bfloat162_rn(acc[mt][nt][0], acc[mt][nt][1]);
            *(__nv_bfloat162*)(out + ((size_t)b * NN + row + 8) * NC + col) =
                __floats2bfloat162_rn(acc[mt][nt][2], acc[mt][nt][3]);
        }
    }
}

// ---------------- gate: d0 reduce + value = sigmoid(Xeff @ Wg^T + bg); emit u, r*h ------
// Prologue reduces this CTA's 64 column sums from g_cpart (also stores g_d0 for final).
__global__ __launch_bounds__(256) void gate_kernel(const float* __restrict__ inputs,
                                                   const float* __restrict__ hx) {
    constexpr int KT = 32;
    __shared__ float Xs[KT][64 + 4];
    __shared__ float Ws[KT][128 + 4];
    __shared__ float sd0[64];
    int r0 = blockIdx.x * 64;
    int t = threadIdx.x, ty = t >> 4, tx = t & 15;
    // --- d0 for rows r0..r0+63 (same batch: 64 | 1024) ---
    {
        int b = r0 >> 10;
        int n0 = r0 & 1023;
        if (t < 64) {
            const float* cp = g_cpart + (size_t)b * 64 * NN + n0 + t;
            float s = 0.f;
#pragma unroll
            for (int i = 0; i < 64; i++) s += cp[(size_t)i * NN];
            s += 1.0f;
            sd0[t] = s;
            g_d0[r0 + t] = s;
        }
    }
    __syncthreads();

    float acc[4][8];
#pragma unroll
    for (int m = 0; m < 4; m++)
#pragma unroll
        for (int n = 0; n < 8; n++) acc[m][n] = 0.f;

    for (int k0 = 0; k0 < 384; k0 += KT) {
        int reg = k0 >> 7;
#pragma unroll
        for (int p = 0; p < 2; p++) {
            int ii = (t >> 3) + p * 32;
            int kq = (t & 7) << 2;
            int r = r0 + ii;
            int f = (k0 + kq) & 127;
            float4 xv = (f < 64) ? *(const float4*)(inputs + (size_t)r * 64 + f)
                                 : *(const float4*)(hx + (size_t)r * 64 + (f - 64));
            if (reg == 1) {
                const __nv_bfloat162* yp = (const __nv_bfloat162*)(g_Y0h + (size_t)r * 128 + f);
                float2 y01 = __bfloat1622float2(yp[0]);
                float2 y23 = __bfloat1622float2(yp[1]);
                float di = 1.f / sd0[ii];
                xv.x = (xv.x + y01.x) * di; xv.y = (xv.y + y01.y) * di;
                xv.z = (xv.z + y23.x) * di; xv.w = (xv.w + y23.y) * di;
            } else if (reg == 2) {
                const __nv_bfloat162* yp = (const __nv_bfloat162*)(g_Y1h + (size_t)r * 128 + f);
                float2 y01 = __bfloat1622float2(yp[0]);
                float2 y23 = __bfloat1622float2(yp[1]);
                float di = 1.f / g_d1[r];
                xv.x = (xv.x + y01.x) * di; xv.y = (xv.y + y01.y) * di;
                xv.z = (xv.z + y23.x) * di; xv.w = (xv.w + y23.y) * di;
            }
            Xs[kq + 0][ii] = xv.x; Xs[kq + 1][ii] = xv.y;
            Xs[kq + 2][ii] = xv.z; Xs[kq + 3][ii] = xv.w;
        }
#pragma unroll
        for (int p = 0; p < 4; p++) {
            int c = (t >> 3) + p * 32;
            int kq = (t & 7) << 2;
            float4 wv = *(const float4*)(g_Wg + c * 384 + k0 + kq);
            Ws[kq + 0][c] = wv.x; Ws[kq + 1][c] = wv.y;
            Ws[kq + 2][c] = wv.z; Ws[kq + 3][c] = wv.w;
        }
        __syncthreads();
#pragma unroll
        for (int kk = 0; kk < KT; kk++) {
            float a[4], wv[8];
#pragma unroll
            for (int m = 0; m < 4; m++) a[m] = Xs[kk][ty * 4 + m];
#pragma unroll
            for (int n = 0; n < 8; n++) wv[n] = Ws[kk][tx * 8 + n];
#pragma unroll
            for (int m = 0; m < 4; m++)
#pragma unroll
                for (int n = 0; n < 8; n++) acc[m][n] = fmaf(a[m], wv[n], acc[m][n]);
        }
        __syncthreads();
    }
#pragma unroll
    for (int m = 0; m < 4; m++) {
        size_t r = (size_t)(r0 + ty * 4 + m);
#pragma unroll
        for (int n = 0; n < 8; n++) {
            int c = tx * 8 + n;
            float v = 1.f / (1.f + expf(-(acc[m][n] + g_bg[c])));
            if (c < 64) {
                float rh = v * hx[r * 64 + c];
                g_rh[r * 64 + c] = rh;
                g_rhh[r * 64 + c] = __float2bfloat16_rn(rh);
            } else {
                g_u[r * 64 + (c - 64)] = v;
            }
        }
    }
}

// ---------------- final: c = tanh(X2eff @ Wc^T + bc); out = u*h + (1-u)*c ----------------
__global__ __launch_bounds__(256) void final_kernel(const float* __restrict__ inputs,
                                                    const float* __restrict__ hx,
                                                    float* __restrict__ out) {
    constexpr int KT = 32;
    __shared__ float Xs[KT][64 + 4];
    __shared__ float Ws[KT][64 + 4];
    int r0 = blockIdx.x * 64;
    int t = threadIdx.x, ty = t >> 4, tx = t & 15;
    float acc[4][4];
#pragma unroll
    for (int m = 0; m < 4; m++)
#pragma unroll
        for (int n = 0; n < 4; n++) acc[m][n] = 0.f;

    for (int k0 = 0; k0 < 384; k0 += KT) {
        int reg = k0 >> 7;
#pragma unroll
        for (int p = 0; p < 2; p++) {
            int ii = (t >> 3) + p * 32;
            int kq = (t & 7) << 2;
            int r = r0 + ii;
            int f = (k0 + kq) & 127;
            float4 xv = (f < 64) ? *(const float4*)(inputs + (size_t)r * 64 + f)
                                 : *(const float4*)(g_rh + (size_t)r * 64 + (f - 64));
            if (reg == 1) {
                const __nv_bfloat162* yp = (f < 64)
                    ? (const __nv_bfloat162*)(g_Y0h + (size_t)r * 128 + f)
                    : (const __nv_bfloat162*)(g_Y0ph + (size_t)r * 64 + (f - 64));
                float2 y01 = __bfloat1622float2(yp[0]);
                float2 y23 = __bfloat1622float2(yp[1]);
                float di = 1.f / g_d0[r];
                xv.x = (xv.x + y01.x) * di; xv.y = (xv.y + y01.y) * di;
                xv.z = (xv.z + y23.x) * di; xv.w = (xv.w + y23.y) * di;
            } else if (reg == 2) {
                const __nv_bfloat162* yp = (f < 64)
                    ? (const __nv_bfloat162*)(g_Y1h + (size_t)r * 128 + f)
                    : (const __nv_bfloat162*)(g_Y1ph + (size_t)r * 64 + (f - 64));
                float2 y01 = __bfloat1622float2(yp[0]);
                float2 y23 = __bfloat1622float2(yp[1]);
                float di = 1.f / g_d1[r];
                xv.x = (xv.x + y01.x) * di; xv.y = (xv.y + y01.y) * di;
                xv.z = (xv.z + y23.x) * di; xv.w = (xv.w + y23.y) * di;
            }
            Xs[kq + 0][ii] = xv.x; Xs[kq + 1][ii] = xv.y;
            Xs[kq + 2][ii] = xv.z; Xs[kq + 3][ii] = xv.w;
        }
#pragma unroll
        for (int p = 0; p < 2; p++) {
            int c = (t >> 3) + p * 32;
            int kq = (t & 7) << 2;
            float4 wv = *(const float4*)(g_Wc + c * 384 + k0 + kq);
            Ws[kq + 0][c] = wv.x; Ws[kq + 1][c] = wv.y;
            Ws[kq + 2][c] = wv.z; Ws[kq + 3][c] = wv.w;
        }
        __syncthreads();
#pragma unroll
        for (int kk = 0; kk < KT; kk++) {
            float a[4], wv[4];
#pragma unroll
            for (int m = 0; m < 4; m++) a[m] = Xs[kk][ty * 4 + m];
#pragma unroll
            for (int n = 0; n < 4; n++) wv[n] = Ws[kk][tx * 4 + n];
#pragma unroll
            for (int m = 0; m < 4; m++)
#pragma unroll
                for (int n = 0; n < 4; n++) acc[m][n] = fmaf(a[m], wv[n], acc[m][n]);
        }
        __syncthreads();
    }
#pragma unroll
    for (int m = 0; m < 4; m++) {
        size_t r = (size_t)(r0 + ty * 4 + m);
#pragma unroll
        for (int n = 0; n < 4; n++) {
            int c = tx * 4 + n;
            float cv = tanhf(acc[m][n] + g_bc[c]);
            float u = g_u[r * 64 + c];
            float h = hx[r * 64 + c];
            out[r * 64 + c] = u * h + (1.f - u) * cv;
        }
    }
}

// ---------------- launch ----------------
extern "C" void kernel_launch(void* const* d_in, const int* in_sizes, int n_in,
                              void* d_out, int out_size) {
    const float* logits = (const float*)d_in[0];
    const float* unoise = (const float*)d_in[1];
    const float* inputs = (const float*)d_in[2];
    const float* hx     = (const float*)d_in[3];
    const float* W0  = (const float*)d_in[4];
    const float* b0  = (const float*)d_in[5];
    const float* W1  = (const float*)d_in[6];
    const float* b1  = (const float*)d_in[7];
    const float* Wc0 = (const float*)d_in[8];
    const float* bc0 = (const float*)d_in[9];
    const float* Wc1 = (const float*)d_in[10];
    const float* bc1 = (const float*)d_in[11];
    float* out = (float*)d_out;

    static bool attr_done = false;
    if (!attr_done) {
        cudaFuncSetAttribute(adj_gemm_bf16<0>, cudaFuncAttributeMaxDynamicSharedMemorySize, 65536);
        cudaFuncSetAttribute(adj_gemm_bf16<1>, cudaFuncAttributeMaxDynamicSharedMemorySize, 49152);
        attr_done = true;
    }

    prep_convert_kernel<<<2096, 256>>>(inputs, hx, W0, b0, W1, b1, Wc0, bc0, Wc1, bc1);
    gumbel_kernel<<<dim3(64, BB), 256>>>(logits, unoise);
    adj_gemm_bf16<0><<<dim3(8, BB, 2), 256, 65536>>>();
    gate_kernel<<<256, 256>>>(inputs, hx);
    adj_gemm_bf16<1><<<dim3(8, BB, 2), 256, 49152>>>();
    final_kernel<<<256, 256>>>(inputs, hx, out);
}